// round 2
// baseline (speedup 1.0000x reference)
#include <cuda_runtime.h>
#include <cuda_bf16.h>

// Problem constants
#define BATCH 8
#define HH 128            // spatial after space-to-depth
#define WW 128
#define HWPIX (HH*WW)     // 16384
#define NPIX (BATCH*HWPIX)// 131072
#define KSQ 256           // squeeze input channels
#define NSQ 128           // squeeze output channels
#define CINC 66           // up channels incl coords
#define TT 9              // K*K
#define NCH 594           // CINC*TT
#define UPC 64

// -------- static device scratch (no allocation allowed) --------
__device__ float g_up[BATCH * 64 * HWPIX];      // squeeze channels 0..63 (32 MB)
__device__ float g_gfs[NCH * 9];                // gf * bn_scale, [c*9+t][u]
__device__ float g_shift[NCH];
__device__ float g_gw[NCH];
__device__ float g_wct[CINC * TT * UPC];        // w_conv transposed: [c][t][o]

// -------- packed fp32x2 FMA (Blackwell FFMA2) --------
__device__ __forceinline__ void ffma2(float2& acc, float2 a, float2 b) {
    asm("fma.rn.f32x2 %0, %1, %2, %0;"
        : "+l"(reinterpret_cast<unsigned long long&>(acc))
        : "l"(reinterpret_cast<unsigned long long const&>(a)),
          "l"(reinterpret_cast<unsigned long long const&>(b)));
}

// -------- FFMA-only exp (x <= 0). rel err ~1e-5, no MUFU --------
__device__ __forceinline__ float fexp_neg(float x) {
    float y = fmaxf(x * 1.4426950408889634f, -100.0f);  // log2(e)
    float fl = floorf(y);
    float r = y - fl;                                   // r in [0,1)
    float p = 1.5403530e-4f;                            // Taylor of 2^r
    p = fmaf(p, r, 1.33335581e-3f);
    p = fmaf(p, r, 9.61812911e-3f);
    p = fmaf(p, r, 5.55041087e-2f);
    p = fmaf(p, r, 2.40226507e-1f);
    p = fmaf(p, r, 6.93147181e-1f);
    p = fmaf(p, r, 1.0f);
    return p * __int_as_float(((int)fl + 127) << 23);
}

// -------- K0: weight prep --------
__global__ void prep_kernel(const float* __restrict__ gf, const float* __restrict__ gamma,
                            const float* __restrict__ beta, const float* __restrict__ mean,
                            const float* __restrict__ var, const float* __restrict__ gw,
                            const float* __restrict__ wconv) {
    int i = blockIdx.x * blockDim.x + threadIdx.x;
    if (i < NCH) {
        float sc = gamma[i] * rsqrtf(var[i] + 1e-5f);
        g_shift[i] = beta[i] - mean[i] * sc;
        g_gw[i] = gw[i];
        #pragma unroll
        for (int u = 0; u < 9; u++) g_gfs[i * 9 + u] = gf[i * 9 + u] * sc;
    }
    if (i < CINC * TT * UPC) {                 // g_wct[ct*64+o] = wconv[o*594 + ct]
        int o = i & 63;
        int ct = i >> 6;
        g_wct[ct * UPC + o] = wconv[o * NCH + ct];
    }
}

// -------- K1: space-to-depth + 1x1 squeeze (SGEMM) --------
// Each block: one output row (b,h): 128 pixels x 128 channels, K=256.
// 256 threads: tr=channel tile (16 x 8ch), tc=pixel tile (16 x 8px).
__global__ __launch_bounds__(256, 2) void squeeze_kernel(
    const float* __restrict__ x, const float* __restrict__ wsq, float* __restrict__ out) {
    __shared__ float As[8][128];   // [k][pixel]
    __shared__ float Bs[8][128];   // [k][out channel]

    int tid = threadIdx.x;
    int bh = blockIdx.x;
    int b = bh >> 7, h = bh & 127;
    int tr = tid >> 4, tc = tid & 15;

    const float* xb = x + b * 64 * 65536;

    float2 acc[8][4];
    #pragma unroll
    for (int i = 0; i < 8; i++)
        #pragma unroll
        for (int j = 0; j < 4; j++) acc[i][j] = make_float2(0.f, 0.f);

    for (int k0 = 0; k0 < KSQ; k0 += 8) {
        #pragma unroll
        for (int i = 0; i < 4; i++) {           // A: pixel gather (space-to-depth)
            int flat = tid + i * 256;
            int m = flat & 127, k = flat >> 7;
            int kg = k0 + k;
            int q = kg >> 6, ci = kg & 63;
            int row = 2 * h + (q & 1);
            int col = 2 * m + (q >> 1);
            As[k][m] = xb[(ci * 256 + row) * 256 + col];
        }
        #pragma unroll
        for (int i = 0; i < 4; i++) {           // B: weights
            int flat = tid + i * 256;
            int k = flat & 7, n = flat >> 3;
            Bs[k][n] = wsq[n * 256 + k0 + k];
        }
        __syncthreads();

        #pragma unroll
        for (int k = 0; k < 8; k++) {
            float4 a0 = *(const float4*)&As[k][tc * 8];
            float4 a1 = *(const float4*)&As[k][tc * 8 + 4];
            float2 ap[4] = { {a0.x, a0.y}, {a0.z, a0.w}, {a1.x, a1.y}, {a1.z, a1.w} };
            float bv[8];
            #pragma unroll
            for (int i = 0; i < 8; i++) bv[i] = Bs[k][tr * 8 + i];
            #pragma unroll
            for (int i = 0; i < 8; i++) {
                float2 bb = make_float2(bv[i], bv[i]);
                #pragma unroll
                for (int j = 0; j < 4; j++) ffma2(acc[i][j], bb, ap[j]);
            }
        }
        __syncthreads();
    }

    // Epilogue: co = tr*8+i owns 8 consecutive pixels (tc*8..+7) -> float4 coalesced
    int m0 = tc * 8;
    int rowoff = h * 128 + m0;
    #pragma unroll
    for (int i = 0; i < 8; i++) {
        int co = tr * 8 + i;
        float4 v0 = make_float4(acc[i][0].x, acc[i][0].y, acc[i][1].x, acc[i][1].y);
        float4 v1 = make_float4(acc[i][2].x, acc[i][2].y, acc[i][3].x, acc[i][3].y);
        float* dst;
        if (co < 64) {
            dst = g_up + ((b * 64 + co) << 14) + rowoff;
        } else {
            int l = co - 64;                      // low channel
            int oc = (l & 1) ? (96 + (l >> 1)) : (32 + (l >> 1));  // channel shuffle
            dst = out + ((b * 128 + oc) << 14) + rowoff;
        }
        *(float4*)dst = v0;
        *(float4*)(dst + 4) = v1;
    }
}

// -------- K2: fused avgpool + softmax weight + depthwise feat + BN/ReLU +
//              reassembly + stride-3 conv (= per-pixel 594x64 contraction) --------
// Block: 16x16 pixel tile, 256 threads, one pixel each. 64 fp32 accumulators/thread.
__global__ __launch_bounds__(256, 2) void carafe_kernel(
    const float* __restrict__ bconv, float* __restrict__ out) {
    __shared__ float tile[18 * 18];
    __shared__ float s_wct[TT * UPC];   // 576
    __shared__ float s_gfs[81];
    __shared__ float s_gw[9];
    __shared__ float s_shift[9];

    int tid = threadIdx.x;
    int b = blockIdx.z;
    int ty0 = blockIdx.y * 16, tx0 = blockIdx.x * 16;
    int py = tid >> 4, px = tid & 15;
    int gy = ty0 + py, gx = tx0 + px;

    const float* upb = g_up + b * 64 * HWPIX;

    float2 acc[32];
    #pragma unroll
    for (int j = 0; j < 32; j++) acc[j] = make_float2(0.f, 0.f);

    for (int c = 0; c < CINC; c++) {
        // ---- stage tile (with halo, zero-padded) + per-channel weights ----
        for (int i = tid; i < 324; i += 256) {
            int ly = i / 18, lx = i - ly * 18;
            int yy = ty0 - 1 + ly, xx = tx0 - 1 + lx;
            float v = 0.f;
            if ((unsigned)yy < 128u && (unsigned)xx < 128u) {
                if (c < 64)      v = upb[c * HWPIX + yy * 128 + xx];
                else if (c == 64) v = (float)xx * (2.0f / 127.0f) - 1.0f;   // xx coord
                else              v = (float)yy * (2.0f / 127.0f) - 1.0f;   // yy coord
            }
            tile[i] = v;
        }
        for (int i = tid; i < TT * UPC; i += 256) s_wct[i] = g_wct[c * (TT * UPC) + i];
        if (tid < 81) s_gfs[tid] = g_gfs[c * 81 + tid];
        if (tid < 9) { s_gw[tid] = g_gw[c * 9 + tid]; s_shift[tid] = g_shift[c * 9 + tid]; }
        __syncthreads();

        // ---- per-pixel: 3x3 neighborhood ----
        float nb[9];
        #pragma unroll
        for (int dy = 0; dy < 3; dy++)
            #pragma unroll
            for (int dx = 0; dx < 3; dx++)
                nb[dy * 3 + dx] = tile[(py + dy) * 18 + (px + dx)];

        // avgpool (always /9, zero pad)
        float pooled = (((nb[0] + nb[1]) + (nb[2] + nb[3])) +
                        ((nb[4] + nb[5]) + (nb[6] + nb[7])) + nb[8]) * (1.0f / 9.0f);

        // softmax over t of pooled * gw[t]
        float sv[9];
        float mx = -1e30f;
        #pragma unroll
        for (int t = 0; t < 9; t++) { sv[t] = pooled * s_gw[t]; mx = fmaxf(mx, sv[t]); }
        float sum = 0.f;
        #pragma unroll
        for (int t = 0; t < 9; t++) { float e = fexp_neg(sv[t] - mx); sv[t] = e; sum += e; }
        float inv = __fdividef(1.0f, sum);

        // feat (depthwise 3x3, scale-folded) -> relu -> * softmax weight
        #pragma unroll
        for (int t = 0; t < 9; t++) {
            float f = s_shift[t];
            #pragma unroll
            for (int u = 0; u < 9; u++) f = fmaf(nb[u], s_gfs[t * 9 + u], f);
            f = fmaxf(f, 0.0f);
            sv[t] = f * sv[t] * inv;
        }

        // contraction: acc[o] += sv[t] * wct[c][t][o]   (packed f32x2, 288 FFMA2)
        #pragma unroll
        for (int t = 0; t < 9; t++) {
            float2 st = make_float2(sv[t], sv[t]);
            const float2* wc = reinterpret_cast<const float2*>(s_wct + t * UPC);
            #pragma unroll
            for (int j = 0; j < 32; j++) ffma2(acc[j], st, wc[j]);
        }
        __syncthreads();
    }

    // ---- epilogue: +bias, channel shuffle (even -> 0..63, odd -> 64..127) ----
    int hw = gy * 128 + gx;
    float* ob = out + b * 128 * HWPIX;
    #pragma unroll
    for (int j = 0; j < 32; j++) {
        float v0 = acc[j].x + bconv[2 * j];
        float v1 = acc[j].y + bconv[2 * j + 1];
        ob[j * HWPIX + hw] = v0;            // even up-channel 2j  -> out channel j
        ob[(64 + j) * HWPIX + hw] = v1;     // odd  up-channel 2j+1-> out channel 64+j
    }
}

extern "C" void kernel_launch(void* const* d_in, const int* in_sizes, int n_in,
                              void* d_out, int out_size) {
    const float* x       = (const float*)d_in[0];
    const float* wsq     = (const float*)d_in[1];
    const float* wgw     = (const float*)d_in[2];
    const float* wgf     = (const float*)d_in[3];
    const float* gamma   = (const float*)d_in[4];
    const float* beta    = (const float*)d_in[5];
    const float* mean    = (const float*)d_in[6];
    const float* var     = (const float*)d_in[7];
    const float* wconv   = (const float*)d_in[8];
    const float* bconv   = (const float*)d_in[9];
    float* out = (float*)d_out;

    prep_kernel<<<(CINC * TT * UPC + 255) / 256, 256>>>(wgf, gamma, beta, mean, var, wgw, wconv);
    squeeze_kernel<<<BATCH * HH, 256>>>(x, wsq, out);
    carafe_kernel<<<dim3(WW / 16, HH / 16, BATCH), 256>>>(bconv, out);
}

// round 3
// speedup vs baseline: 1.3272x; 1.3272x over previous
#include <cuda_runtime.h>
#include <cuda_bf16.h>

#define BATCH 8
#define HH 128
#define WW 128
#define HWPIX (HH*WW)
#define KSQ 256
#define CINC 66
#define TT 9
#define NCH 594
#define UPC 64
#define SMALLC 112   // per-channel packed small params

// -------- static device scratch --------
__device__ float g_up[BATCH * 64 * HWPIX];   // squeeze up-channels (32 MB)
__device__ float g_wct[CINC * TT * UPC];     // w_conv transposed [c][t][o]
__device__ float g_small[CINC * SMALLC];     // per c: [0..89] gfs t-pairs, [90..99] shift, [100..108] gw*log2e/9

// -------- packed fp32x2 FMA --------
__device__ __forceinline__ void ffma2(float2& acc, float2 a, float2 b) {
    asm("fma.rn.f32x2 %0, %1, %2, %0;"
        : "+l"(reinterpret_cast<unsigned long long&>(acc))
        : "l"(reinterpret_cast<unsigned long long const&>(a)),
          "l"(reinterpret_cast<unsigned long long const&>(b)));
}

// -------- 2^y, deg-5 poly (rel err < 1e-4), no MUFU --------
__device__ __forceinline__ float fexp2p(float y) {
    y = fminf(fmaxf(y, -120.f), 120.f);
    float fl = floorf(y);
    float r = y - fl;
    float p = 1.33335581e-3f;
    p = fmaf(p, r, 9.61812911e-3f);
    p = fmaf(p, r, 5.55041087e-2f);
    p = fmaf(p, r, 2.40226507e-1f);
    p = fmaf(p, r, 6.93147181e-1f);
    p = fmaf(p, r, 1.0f);
    return p * __int_as_float(((int)fl + 127) << 23);
}

// -------- K1: prep (first 178 blocks) + space-to-depth + 1x1 squeeze GEMM --------
__global__ __launch_bounds__(256, 2) void squeeze_kernel(
    const float* __restrict__ x, const float* __restrict__ wsq, float* __restrict__ out,
    const float* __restrict__ gf, const float* __restrict__ gamma,
    const float* __restrict__ beta, const float* __restrict__ mean,
    const float* __restrict__ var, const float* __restrict__ gw,
    const float* __restrict__ wconv) {
    __shared__ float  As[2][8][128];
    __shared__ float2 Bs2[2][8][130];   // padded to kill STS bank conflicts

    int tid = threadIdx.x;
    int bid = blockIdx.x;

    // ---- prep chunks (tiny; carafe launches only after this kernel completes) ----
    if (bid < 149) {
        int idx = bid * 256 + tid;                       // w_conv transpose
        if (idx < NCH * UPC) {
            int ct = idx >> 6, o = idx & 63;
            g_wct[ct * UPC + o] = wconv[o * NCH + ct];
        }
    } else if (bid < 178) {
        int idx = (bid - 149) * 256 + tid;               // packed small params
        if (idx < CINC * SMALLC) {
            int c = idx / SMALLC, s = idx - c * SMALLC;
            float v = 0.f;
            if (s < 90) {
                int q = s >> 1, lane = s & 1;
                int u = q / 5, tp = q - u * 5, t = 2 * tp + lane;
                if (t < 9) {
                    int i = c * 9 + t;
                    float sc = gamma[i] * rsqrtf(var[i] + 1e-5f);
                    v = gf[i * 9 + u] * sc;
                }
            } else if (s < 100) {
                int t = s - 90;
                if (t < 9) {
                    int i = c * 9 + t;
                    float sc = gamma[i] * rsqrtf(var[i] + 1e-5f);
                    v = beta[i] - mean[i] * sc;
                }
            } else if (s < 109) {
                v = gw[c * 9 + (s - 100)] * 0.160299448987663f;   // log2(e)/9
            }
            g_small[idx] = v;
        }
    }

    // ---- squeeze GEMM: block = (b,h) row, 128 px x 128 ch, K=256 ----
    int b = bid >> 7, h = bid & 127;
    int tr = tid >> 4, tc = tid & 15;
    const float* xb = x + b * 64 * 65536;

    float2 acc[8][4];
    #pragma unroll
    for (int i = 0; i < 8; i++)
        #pragma unroll
        for (int j = 0; j < 4; j++) acc[i][j] = make_float2(0.f, 0.f);

    float rA[4], rB[4];
    // prefetch tile 0
    #pragma unroll
    for (int i = 0; i < 4; i++) {
        int flat = tid + i * 256;
        int m = flat & 127, k = flat >> 7;
        int q = k >> 6, ci = k & 63;
        rA[i] = xb[(ci * 256 + 2 * h + (q & 1)) * 256 + 2 * m + (q >> 1)];
    }
    #pragma unroll
    for (int i = 0; i < 4; i++) {
        int flat = tid + i * 256;
        int k = flat & 7, n = flat >> 3;
        rB[i] = wsq[n * 256 + k];
    }

    int p = 0;
    for (int t = 0; t < 32; ++t) {
        // store staged tile
        #pragma unroll
        for (int i = 0; i < 4; i++) {
            int flat = tid + i * 256;
            As[p][flat >> 7][flat & 127] = rA[i];
        }
        #pragma unroll
        for (int i = 0; i < 4; i++) {
            int flat = tid + i * 256;
            Bs2[p][flat & 7][flat >> 3] = make_float2(rB[i], rB[i]);
        }
        // prefetch next tile
        if (t < 31) {
            int k0 = (t + 1) * 8;
            #pragma unroll
            for (int i = 0; i < 4; i++) {
                int flat = tid + i * 256;
                int m = flat & 127, kg = k0 + (flat >> 7);
                int q = kg >> 6, ci = kg & 63;
                rA[i] = xb[(ci * 256 + 2 * h + (q & 1)) * 256 + 2 * m + (q >> 1)];
            }
            #pragma unroll
            for (int i = 0; i < 4; i++) {
                int flat = tid + i * 256;
                rB[i] = wsq[(flat >> 3) * 256 + k0 + (flat & 7)];
            }
        }
        __syncthreads();
        #pragma unroll
        for (int k = 0; k < 8; k++) {
            float4 a0 = *(const float4*)&As[p][k][tc * 8];
            float4 a1 = *(const float4*)&As[p][k][tc * 8 + 4];
            float2 av[4] = { {a0.x, a0.y}, {a0.z, a0.w}, {a1.x, a1.y}, {a1.z, a1.w} };
            float2 bv[8];
            #pragma unroll
            for (int i = 0; i < 8; i++) bv[i] = Bs2[p][k][tr * 8 + i];
            #pragma unroll
            for (int i = 0; i < 8; i++)
                #pragma unroll
                for (int j = 0; j < 4; j++) ffma2(acc[i][j], bv[i], av[j]);
        }
        p ^= 1;
    }

    // epilogue: ch co -> g_up (co<64) or out low channels (shuffled)
    int rowoff = h * 128 + tc * 8;
    #pragma unroll
    for (int i = 0; i < 8; i++) {
        int co = tr * 8 + i;
        float4 v0 = make_float4(acc[i][0].x, acc[i][0].y, acc[i][1].x, acc[i][1].y);
        float4 v1 = make_float4(acc[i][2].x, acc[i][2].y, acc[i][3].x, acc[i][3].y);
        float* dst;
        if (co < 64) {
            dst = g_up + ((b * 64 + co) << 14) + rowoff;
        } else {
            int l = co - 64;
            int oc = (l & 1) ? (96 + (l >> 1)) : (32 + (l >> 1));
            dst = out + ((b * 128 + oc) << 14) + rowoff;
        }
        *(float4*)dst = v0;
        *(float4*)(dst + 4) = v1;
    }
}

// -------- carafe tile value (with halo, coords channels computed) --------
__device__ __forceinline__ float tile_val(const float* __restrict__ upb, int c,
                                          int ty0, int tx0, int i) {
    int ly = i / 18, lx = i - ly * 18;
    int yy = ty0 - 1 + ly, xx = tx0 - 1 + lx;
    if ((unsigned)yy >= 128u || (unsigned)xx >= 128u) return 0.f;
    if (c < 64) return upb[c * HWPIX + yy * 128 + xx];
    if (c == 64) return (float)xx * (2.0f / 127.0f) - 1.0f;
    return (float)yy * (2.0f / 127.0f) - 1.0f;
}

// -------- K2: fused CARAFE tail; phaseA per-pixel sv, phaseB 8px x 8ch GEMM --------
__global__ __launch_bounds__(256, 2) void carafe_kernel(
    const float* __restrict__ bconv, float* __restrict__ out) {
    __shared__ __align__(16) float  s_tile[2][324];
    __shared__ __align__(16) float  s_sv[2][TT][256];
    __shared__ __align__(16) float2 s_wct2[3][TT][UPC];   // duplicated {w,w}
    __shared__ __align__(16) float  s_small[2][SMALLC];

    int tid = threadIdx.x;
    int b = blockIdx.z;
    int ty0 = blockIdx.y * 16, tx0 = blockIdx.x * 16;
    int py = tid >> 4, px = tid & 15;

    int pxg = tid & 31, chg = tid >> 5;
    int px0 = pxg * 8, ch0 = chg * 8;

    const float* upb = g_up + b * 64 * HWPIX;

    float2 acc[4][8];
    #pragma unroll
    for (int pj = 0; pj < 4; pj++)
        #pragma unroll
        for (int j = 0; j < 8; j++) acc[pj][j] = make_float2(0.f, 0.f);

    // ---- preamble: stage c=0 ----
    {
        s_tile[0][tid] = tile_val(upb, 0, ty0, tx0, tid);
        if (tid < 68) s_tile[0][tid + 256] = tile_val(upb, 0, ty0, tx0, tid + 256);
        float w0 = g_wct[tid], w1 = g_wct[256 + tid];
        s_wct2[0][tid >> 6][tid & 63] = make_float2(w0, w0);
        s_wct2[0][(tid + 256) >> 6][tid & 63] = make_float2(w1, w1);
        if (tid < 64) {
            float w2 = g_wct[512 + tid];
            s_wct2[0][8][tid] = make_float2(w2, w2);
        }
        if (tid < 109) s_small[0][tid] = g_small[tid];
    }
    __syncthreads();

    for (int c = 0; c < CINC; c++) {
        int cb = c & 1;
        int ws = c % 3;
        int c1 = c + 1;

        // ---- prefetch next channel into registers (latency hidden by phaseA) ----
        float r_t0 = 0.f, r_t1 = 0.f, r_w0 = 0.f, r_w1 = 0.f, r_w2 = 0.f, r_s = 0.f;
        if (c1 < CINC) {
            r_t0 = tile_val(upb, c1, ty0, tx0, tid);
            if (tid < 68) r_t1 = tile_val(upb, c1, ty0, tx0, tid + 256);
            r_w0 = g_wct[c1 * 576 + tid];
            r_w1 = g_wct[c1 * 576 + 256 + tid];
            if (tid < 64) r_w2 = g_wct[c1 * 576 + 512 + tid];
            if (tid < 109) r_s = g_small[c1 * SMALLC + tid];
        }

        // ---- phaseA: per-pixel sv[9] ----
        {
            const float* tl = s_tile[cb];
            const float* sm = s_small[cb];
            float nb[9];
            #pragma unroll
            for (int dy = 0; dy < 3; dy++)
                #pragma unroll
                for (int dx = 0; dx < 3; dx++)
                    nb[dy * 3 + dx] = tl[(py + dy) * 18 + (px + dx)];

            float rawsum = (((nb[0] + nb[1]) + (nb[2] + nb[3])) +
                            ((nb[4] + nb[5]) + (nb[6] + nb[7])) + nb[8]);

            // softmax numerators (no max-sub; args tiny), gw has log2e/9 folded
            float e[9], esum = 0.f;
            #pragma unroll
            for (int t = 0; t < 9; t++) {
                e[t] = fexp2p(rawsum * sm[100 + t]);
                esum += e[t];
            }
            float inv = __fdividef(1.0f, esum);

            // feat: packed over t-pairs, BN shift pre-paired as init
            float2 f2[5];
            #pragma unroll
            for (int tp = 0; tp < 5; tp++)
                f2[tp] = *(const float2*)&sm[90 + 2 * tp];
            #pragma unroll
            for (int u = 0; u < 9; u++) {
                float2 nd = make_float2(nb[u], nb[u]);
                const float2* gp = (const float2*)&sm[2 * (u * 5)];
                #pragma unroll
                for (int tp = 0; tp < 5; tp++) ffma2(f2[tp], nd, gp[tp]);
            }
            #pragma unroll
            for (int t = 0; t < 9; t++) {
                float f = (t & 1) ? f2[t >> 1].y : f2[t >> 1].x;
                f = fmaxf(f, 0.f);
                s_sv[cb][t][tid] = f * e[t] * inv;
            }
        }

        // ---- store staged next channel ----
        if (c1 < CINC) {
            int nb2 = c1 & 1, ws2 = c1 % 3;
            s_tile[nb2][tid] = r_t0;
            if (tid < 68) s_tile[nb2][tid + 256] = r_t1;
            s_wct2[ws2][tid >> 6][tid & 63] = make_float2(r_w0, r_w0);
            s_wct2[ws2][(tid + 256) >> 6][tid & 63] = make_float2(r_w1, r_w1);
            if (tid < 64) s_wct2[ws2][8][tid] = make_float2(r_w2, r_w2);
            if (tid < 109) s_small[nb2][tid] = r_s;
        }
        __syncthreads();

        // ---- phaseB: contraction, k = 9 taps ----
        #pragma unroll
        for (int t = 0; t < 9; t++) {
            float4 a0 = *(const float4*)&s_sv[cb][t][px0];
            float4 a1 = *(const float4*)&s_sv[cb][t][px0 + 4];
            float2 av[4] = { {a0.x, a0.y}, {a0.z, a0.w}, {a1.x, a1.y}, {a1.z, a1.w} };
            const float2* bp = &s_wct2[ws][t][ch0];
            float2 bv[8];
            #pragma unroll
            for (int j = 0; j < 8; j++) bv[j] = bp[j];
            #pragma unroll
            for (int j = 0; j < 8; j++)
                #pragma unroll
                for (int pj = 0; pj < 4; pj++) ffma2(acc[pj][j], bv[j], av[pj]);
        }
    }

    // ---- epilogue: bias + channel shuffle, float4 stores ----
    int hwbase = (ty0 + (px0 >> 4)) * 128 + tx0 + (px0 & 15);
    float* ob = out + b * 128 * HWPIX;
    #pragma unroll
    for (int j = 0; j < 8; j++) {
        int u = ch0 + j;
        int oc = (u & 1) ? (64 + (u >> 1)) : (u >> 1);
        float bias = bconv[u];
        float4 v0 = make_float4(acc[0][j].x + bias, acc[0][j].y + bias,
                                acc[1][j].x + bias, acc[1][j].y + bias);
        float4 v1 = make_float4(acc[2][j].x + bias, acc[2][j].y + bias,
                                acc[3][j].x + bias, acc[3][j].y + bias);
        float* dst = ob + (oc << 14) + hwbase;
        *(float4*)dst = v0;
        *(float4*)(dst + 4) = v1;
    }
}

extern "C" void kernel_launch(void* const* d_in, const int* in_sizes, int n_in,
                              void* d_out, int out_size) {
    const float* x     = (const float*)d_in[0];
    const float* wsq   = (const float*)d_in[1];
    const float* wgw   = (const float*)d_in[2];
    const float* wgf   = (const float*)d_in[3];
    const float* gamma = (const float*)d_in[4];
    const float* beta  = (const float*)d_in[5];
    const float* mean  = (const float*)d_in[6];
    const float* var   = (const float*)d_in[7];
    const float* wconv = (const float*)d_in[8];
    const float* bconv = (const float*)d_in[9];
    float* out = (float*)d_out;

    squeeze_kernel<<<BATCH * HH, 256>>>(x, wsq, out, wgf, gamma, beta, mean, var, wgw, wconv);
    carafe_kernel<<<dim3(WW / 16, HH / 16, BATCH), 256>>>(bconv, out);
}

// round 8
// speedup vs baseline: 1.6212x; 1.2215x over previous
#include <cuda_runtime.h>
#include <cuda_bf16.h>
#include <cstdint>

#define BATCH 8
#define HWPIX 16384
#define CINC 66
#define TT 9
#define NCH 594
#define SMALLC 112
#define A_STRIDE 20   // fp32 words per A row (80B): 16 used + 4 pad (bank skew)

// ---------------- static device scratch ----------------
__device__ float    g_up[BATCH * 64 * HWPIX];   // squeeze up-channels (32 MB)
__device__ unsigned g_wbf[CINC * 1024];         // fragment-major bf16 B: [c][chunk2][lane32][ntile8][reg2]
__device__ float    g_small[CINC * SMALLC];     // [0..89] gfs t-pairs, [90..99] shift, [100..108] gw*log2e/9

// ---------------- helpers ----------------
__device__ __forceinline__ void ffma2(float2& acc, float2 a, float2 b) {
    asm("fma.rn.f32x2 %0, %1, %2, %0;"
        : "+l"(reinterpret_cast<unsigned long long&>(acc))
        : "l"(reinterpret_cast<unsigned long long const&>(a)),
          "l"(reinterpret_cast<unsigned long long const&>(b)));
}
__device__ __forceinline__ float fexp2p(float y) {
    y = fminf(fmaxf(y, -120.f), 120.f);
    float fl = floorf(y);
    float r = y - fl;
    float p = 1.33335581e-3f;
    p = fmaf(p, r, 9.61812911e-3f);
    p = fmaf(p, r, 5.55041087e-2f);
    p = fmaf(p, r, 2.40226507e-1f);
    p = fmaf(p, r, 6.93147181e-1f);
    p = fmaf(p, r, 1.0f);
    return p * __int_as_float(((int)fl + 127) << 23);
}
__device__ __forceinline__ unsigned short bfbits(float v) {
    __nv_bfloat16 h = __float2bfloat16(v);
    return *reinterpret_cast<unsigned short*>(&h);
}
__device__ __forceinline__ float bf2f(unsigned short u) {
    __nv_bfloat16 h = *reinterpret_cast<__nv_bfloat16*>(&u);
    return __bfloat162float(h);
}
__device__ __forceinline__ void mma_bf16(float* d, unsigned a0, unsigned a1,
                                         unsigned a2, unsigned a3,
                                         unsigned b0, unsigned b1) {
    asm volatile("mma.sync.aligned.m16n8k16.row.col.f32.bf16.bf16.f32 "
        "{%0,%1,%2,%3}, {%4,%5,%6,%7}, {%8,%9}, {%0,%1,%2,%3};"
        : "+f"(d[0]), "+f"(d[1]), "+f"(d[2]), "+f"(d[3])
        : "r"(a0), "r"(a1), "r"(a2), "r"(a3), "r"(b0), "r"(b1));
}

// B element for fragment-major prep. K slots: 0-8 = hi(w[t]), 9-17 = hi(w[t]),
// 18-26 = lo(w[t]), 27-31 = 0.  (A rows carry hi|lo|hi -> 3-term bf16 split.)
__device__ __forceinline__ unsigned short wb_elem(const float* __restrict__ wconv,
                                                  int c, int col, int k) {
    if (k >= 27) return 0;
    int t = (k < 9) ? k : (k < 18 ? k - 9 : k - 18);
    float wv = wconv[col * NCH + c * 9 + t];
    unsigned short hi = bfbits(wv);
    if (k < 18) return hi;
    return bfbits(wv - bf2f(hi));
}

// ================= K1: prep + space-to-depth + 1x1 squeeze GEMM =================
__global__ __launch_bounds__(256, 2) void squeeze_kernel(
    const float* __restrict__ x, const float* __restrict__ wsq, float* __restrict__ out,
    const float* __restrict__ gf, const float* __restrict__ gamma,
    const float* __restrict__ beta, const float* __restrict__ mean,
    const float* __restrict__ var, const float* __restrict__ gw,
    const float* __restrict__ wconv) {
    __shared__ float  As[2][8][128];
    __shared__ float2 Bs2[2][8][130];

    int tid = threadIdx.x;
    int bid = blockIdx.x;

    // ---- prep chunks (first 293 GEMM blocks) ----
    if (bid < 264) {
        int idx = bid * 256 + tid;                   // < 66*1024 = 67584
        int c = idx >> 10;
        int r = idx & 1023;
        int chunk = r >> 9;
        int lane2 = (r >> 4) & 31;
        int id = r & 15;
        int ntile = id >> 1, reg = id & 1;
        int gid2 = lane2 >> 2, tig2 = lane2 & 3;
        int col = ntile * 8 + gid2;
        int k0 = chunk * 16 + tig2 * 2 + reg * 8;
        unsigned short e0 = wb_elem(wconv, c, col, k0);
        unsigned short e1 = wb_elem(wconv, c, col, k0 + 1);
        g_wbf[idx] = (unsigned)e0 | ((unsigned)e1 << 16);
    } else if (bid < 293) {
        int idx = (bid - 264) * 256 + tid;
        if (idx < CINC * SMALLC) {
            int c = idx / SMALLC, s = idx - c * SMALLC;
            float v = 0.f;
            if (s < 90) {
                int q = s >> 1, lane = s & 1;
                int u = q / 5, tp = q - u * 5, t = 2 * tp + lane;
                if (t < 9) {
                    int i = c * 9 + t;
                    float sc = gamma[i] * rsqrtf(var[i] + 1e-5f);
                    v = gf[i * 9 + u] * sc;
                }
            } else if (s < 100) {
                int t = s - 90;
                if (t < 9) {
                    int i = c * 9 + t;
                    float sc = gamma[i] * rsqrtf(var[i] + 1e-5f);
                    v = beta[i] - mean[i] * sc;
                }
            } else if (s < 109) {
                v = gw[c * 9 + (s - 100)] * 0.160299448987663f;  // log2(e)/9
            }
            g_small[idx] = v;
        }
    }

    // ---- squeeze GEMM: block = (b,h) row, 128 px x 128 ch, K=256 ----
    int b = bid >> 7, h = bid & 127;
    int tr = tid >> 4, tc = tid & 15;
    const float* xb = x + b * 64 * 65536;

    float2 acc[8][4];
    #pragma unroll
    for (int i = 0; i < 8; i++)
        #pragma unroll
        for (int j = 0; j < 4; j++) acc[i][j] = make_float2(0.f, 0.f);

    float rA[4], rB[4];
    #pragma unroll
    for (int i = 0; i < 4; i++) {
        int flat = tid + i * 256;
        int m = flat & 127, k = flat >> 7;
        int q = k >> 6, ci = k & 63;
        rA[i] = xb[(ci * 256 + 2 * h + (q & 1)) * 256 + 2 * m + (q >> 1)];
    }
    #pragma unroll
    for (int i = 0; i < 4; i++) {
        int flat = tid + i * 256;
        rB[i] = wsq[(flat >> 3) * 256 + (flat & 7)];
    }

    int p = 0;
    for (int t = 0; t < 32; ++t) {
        #pragma unroll
        for (int i = 0; i < 4; i++) {
            int flat = tid + i * 256;
            As[p][flat >> 7][flat & 127] = rA[i];
        }
        #pragma unroll
        for (int i = 0; i < 4; i++) {
            int flat = tid + i * 256;
            Bs2[p][flat & 7][flat >> 3] = make_float2(rB[i], rB[i]);
        }
        if (t < 31) {
            int k0 = (t + 1) * 8;
            #pragma unroll
            for (int i = 0; i < 4; i++) {
                int flat = tid + i * 256;
                int m = flat & 127, kg = k0 + (flat >> 7);
                int q = kg >> 6, ci = kg & 63;
                rA[i] = xb[(ci * 256 + 2 * h + (q & 1)) * 256 + 2 * m + (q >> 1)];
            }
            #pragma unroll
            for (int i = 0; i < 4; i++) {
                int flat = tid + i * 256;
                rB[i] = wsq[(flat >> 3) * 256 + k0 + (flat & 7)];
            }
        }
        __syncthreads();
        #pragma unroll
        for (int k = 0; k < 8; k++) {
            float4 a0 = *(const float4*)&As[p][k][tc * 8];
            float4 a1 = *(const float4*)&As[p][k][tc * 8 + 4];
            float2 av[4] = { {a0.x, a0.y}, {a0.z, a0.w}, {a1.x, a1.y}, {a1.z, a1.w} };
            float4 bq[4];
            #pragma unroll
            for (int i = 0; i < 4; i++) bq[i] = *(const float4*)&Bs2[p][k][tr * 8 + i * 2];
            float2 bv[8];
            #pragma unroll
            for (int i = 0; i < 4; i++) {
                bv[2 * i]     = make_float2(bq[i].x, bq[i].y);
                bv[2 * i + 1] = make_float2(bq[i].z, bq[i].w);
            }
            #pragma unroll
            for (int i = 0; i < 8; i++)
                #pragma unroll
                for (int j = 0; j < 4; j++) ffma2(acc[i][j], bv[i], av[j]);
        }
        p ^= 1;
    }

    int rowoff = h * 128 + tc * 8;
    #pragma unroll
    for (int i = 0; i < 8; i++) {
        int co = tr * 8 + i;
        float4 v0 = make_float4(acc[i][0].x, acc[i][0].y, acc[i][1].x, acc[i][1].y);
        float4 v1 = make_float4(acc[i][2].x, acc[i][2].y, acc[i][3].x, acc[i][3].y);
        float* dst;
        if (co < 64) {
            dst = g_up + ((b * 64 + co) << 14) + rowoff;
        } else {
            int l = co - 64;
            int oc = (l & 1) ? (96 + (l >> 1)) : (32 + (l >> 1));
            dst = out + ((b * 128 + oc) << 14) + rowoff;
        }
        *(float4*)dst = v0;
        *(float4*)(dst + 4) = v1;
    }
}

// ================= K2: fused CARAFE tail, mma.sync bf16 contraction =================
// Block = 2 spatial rows (M=256 px), 256 threads (8 warps), 1 px/thread in phaseA.
// Warp tile: 4 Mtiles (64 px) x 4 Ntiles (32 n). A: [px][32 k-slots] bf16 in smem.

__device__ __forceinline__ float rowval(const float* __restrict__ upb, int c, int gy, int gx) {
    if ((unsigned)gy >= 128u || (unsigned)gx >= 128u) return 0.f;
    if (c < 64) return upb[c * HWPIX + gy * 128 + gx];
    if (c == 64) return (float)gx * (2.0f / 127.0f) - 1.0f;
    return (float)gy * (2.0f / 127.0f) - 1.0f;
}

__global__ __launch_bounds__(256, 2) void carafe_kernel(
    const float* __restrict__ bconv, float* __restrict__ out) {
    __shared__ float smA[2 * 256 * A_STRIDE];   // 40960 B (also epilogue transpose buf)
    __shared__ float smRows[2 * 4 * 132];
    __shared__ float smSmall[2 * SMALLC];
    __shared__ float smBias[64];

    int tid = threadIdx.x;
    int lane = tid & 31, w = tid >> 5;
    int gid = lane >> 2, tig = lane & 3;
    int mg = w & 3, ng = w >> 2;
    int bidx = blockIdx.x;
    int b = bidx >> 6;
    int gy0 = (bidx & 63) * 2;
    int row = tid >> 7, gx = tid & 127;
    const float* upb = g_up + b * 64 * HWPIX;

    float acc[4][4][4];
    #pragma unroll
    for (int i = 0; i < 4; i++)
        #pragma unroll
        for (int j = 0; j < 4; j++)
            #pragma unroll
            for (int k = 0; k < 4; k++) acc[i][j][k] = 0.f;

    // stage c = 0
    for (int i = tid; i < 520; i += 256) {
        int r = i / 130, col = i - r * 130;
        smRows[r * 132 + col] = rowval(upb, 0, gy0 - 1 + r, col - 1);
    }
    if (tid < SMALLC) smSmall[tid] = g_small[tid];
    if (tid < 64) smBias[tid] = bconv[tid];
    __syncthreads();

    for (int c = 0; c < CINC; c++) {
        int cb = c & 1, nb2 = cb ^ 1, c1 = c + 1;

        // ---- B fragments for current channel (L2-resident; latency hidden by phaseA) ----
        const uint4* wb = (const uint4*)(g_wbf + c * 1024);
        int boff = (lane * 16 + ng * 8) >> 2;
        uint4 b00 = wb[boff];
        uint4 b01 = wb[boff + 1];
        uint4 b10 = wb[boff + 128];
        uint4 b11 = wb[boff + 129];

        // ---- prefetch next channel rows/small ----
        float rt[3] = {0.f, 0.f, 0.f};
        float rs = 0.f;
        if (c1 < CINC) {
            #pragma unroll
            for (int j = 0; j < 3; j++) {
                int i = tid + j * 256;
                if (i < 520) {
                    int r = i / 130, col = i - r * 130;
                    rt[j] = rowval(upb, c1, gy0 - 1 + r, col - 1);
                }
            }
            if (tid < SMALLC) rs = g_small[c1 * SMALLC + tid];
        }

        // ---- phaseA: per-pixel sv[9] -> bf16 hi/lo packed A row ----
        unsigned u[16];
        {
            const float* rows = smRows + cb * 528;
            const float* sm   = smSmall + cb * SMALLC;
            float nbv[9];
            #pragma unroll
            for (int dy = 0; dy < 3; dy++)
                #pragma unroll
                for (int dx = 0; dx < 3; dx++)
                    nbv[dy * 3 + dx] = rows[(row + dy) * 132 + gx + dx];

            float rawsum = (((nbv[0] + nbv[1]) + (nbv[2] + nbv[3])) +
                            ((nbv[4] + nbv[5]) + (nbv[6] + nbv[7])) + nbv[8]);
            float e[9], esum = 0.f;
            #pragma unroll
            for (int t = 0; t < 9; t++) { e[t] = fexp2p(rawsum * sm[100 + t]); esum += e[t]; }
            float inv = __fdividef(1.0f, esum);

            float2 f2[5];
            #pragma unroll
            for (int tp = 0; tp < 5; tp++) f2[tp] = *(const float2*)&sm[90 + 2 * tp];
            #pragma unroll
            for (int uu = 0; uu < 9; uu++) {
                float2 nd = make_float2(nbv[uu], nbv[uu]);
                const float2* gp = (const float2*)&sm[2 * (uu * 5)];
                #pragma unroll
                for (int tp = 0; tp < 5; tp++) ffma2(f2[tp], nd, gp[tp]);
            }
            unsigned short hb[9], lb[9];
            #pragma unroll
            for (int t = 0; t < 9; t++) {
                float f = (t & 1) ? f2[t >> 1].y : f2[t >> 1].x;
                f = fmaxf(f, 0.f);
                float sv = f * e[t] * inv;
                hb[t] = bfbits(sv);
                lb[t] = bfbits(sv - bf2f(hb[t]));
            }
            // K slots: 0-8 hi, 9-17 lo, 18-26 hi, 27-31 zero
            u[0] = (unsigned)hb[0] | ((unsigned)hb[1] << 16);
            u[1] = (unsigned)hb[2] | ((unsigned)hb[3] << 16);
            u[2] = (unsigned)hb[4] | ((unsigned)hb[5] << 16);
            u[3] = (unsigned)hb[6] | ((unsigned)hb[7] << 16);
            u[4] = (unsigned)hb[8] | ((unsigned)lb[0] << 16);
            u[5] = (unsigned)lb[1] | ((unsigned)lb[2] << 16);
            u[6] = (unsigned)lb[3] | ((unsigned)lb[4] << 16);
            u[7] = (unsigned)lb[5] | ((unsigned)lb[6] << 16);
            u[8] = (unsigned)lb[7] | ((unsigned)lb[8] << 16);
            u[9] = u[0]; u[10] = u[1]; u[11] = u[2]; u[12] = u[3];
            u[13] = (unsigned)hb[8];
            u[14] = 0u; u[15] = 0u;
        }

        // ---- STS: A row + next channel staging ----
        {
            uint4* ap = (uint4*)(smA + cb * (256 * A_STRIDE) + tid * A_STRIDE);
            ap[0] = make_uint4(u[0], u[1], u[2], u[3]);
            ap[1] = make_uint4(u[4], u[5], u[6], u[7]);
            ap[2] = make_uint4(u[8], u[9], u[10], u[11]);
            ap[3] = make_uint4(u[12], u[13], u[14], u[15]);
        }
        if (c1 < CINC) {
            float* rowsN = smRows + nb2 * 528;
            #pragma unroll
            for (int j = 0; j < 3; j++) {
                int i = tid + j * 256;
                if (i < 520) {
                    int r = i / 130, col = i - r * 130;
                    rowsN[r * 132 + col] = rt[j];
                }
            }
            if (tid < SMALLC) smSmall[nb2 * SMALLC + tid] = rs;
        }
        __syncthreads();

        // ---- phaseB: mma over A[cb] ----
        const float* Ab = smA + cb * (256 * A_STRIDE);
        #pragma unroll
        for (int chunk = 0; chunk < 2; chunk++) {
            unsigned breg[8];
            if (chunk == 0) {
                breg[0] = b00.x; breg[1] = b00.y; breg[2] = b00.z; breg[3] = b00.w;
                breg[4] = b01.x; breg[5] = b01.y; breg[6] = b01.z; breg[7] = b01.w;
            } else {
                breg[0] = b10.x; breg[1] = b10.y; breg[2] = b10.z; breg[3] = b10.w;
                breg[4] = b11.x; breg[5] = b11.y; breg[6] = b11.z; breg[7] = b11.w;
            }
            #pragma unroll
            for (int mt = 0; mt < 4; mt++) {
                int r0 = mg * 64 + mt * 16 + gid;
                const unsigned* base = (const unsigned*)(Ab + r0 * A_STRIDE) + chunk * 8 + tig;
                unsigned a0 = base[0];
                unsigned a2 = base[4];
                unsigned a1 = base[8 * A_STRIDE];
                unsigned a3 = base[8 * A_STRIDE + 4];
                #pragma unroll
                for (int nt = 0; nt < 4; nt++)
                    mma_bf16(acc[mt][nt], a0, a1, a2, a3, breg[nt * 2], breg[nt * 2 + 1]);
            }
        }
    }

    // ---- epilogue: transpose via smem (stride 288, px-chunk skew 36), bias, shuffle ----
    __syncthreads();
    float* trans = smA;
    #pragma unroll
    for (int pass = 0; pass < 2; pass++) {
        if (pass) __syncthreads();
        if (ng == pass) {
            #pragma unroll
            for (int mt = 0; mt < 4; mt++) {
                int px = mg * 64 + mt * 16 + gid;
                int pb = (px >> 5) * 36 + (px & 31);
                #pragma unroll
                for (int nt = 0; nt < 4; nt++) {
                    int nl = nt * 8 + tig * 2;
                    trans[nl * 288 + pb]           = acc[mt][nt][0];
                    trans[(nl + 1) * 288 + pb]     = acc[mt][nt][1];
                    trans[nl * 288 + pb + 8]       = acc[mt][nt][2];
                    trans[(nl + 1) * 288 + pb + 8] = acc[mt][nt][3];
                }
            }
        }
        __syncthreads();
        int nl = tid >> 3, k = tid & 7;
        int uch = pass * 32 + nl;
        int oc = (uch & 1) ? (64 + (uch >> 1)) : (uch >> 1);
        float bias = smBias[uch];
        const float* src = trans + nl * 288 + k * 36;
        float* dst = out + (b << 21) + (oc << 14) + gy0 * 128 + k * 32;
        #pragma unroll
        for (int j = 0; j < 8; j++) {
            float4 v = *(const float4*)(src + j * 4);
            v.x += bias; v.y += bias; v.z += bias; v.w += bias;
            *(float4*)(dst + j * 4) = v;
        }
    }
}

extern "C" void kernel_launch(void* const* d_in, const int* in_sizes, int n_in,
                              void* d_out, int out_size) {
    const float* x     = (const float*)d_in[0];
    const float* wsq   = (const float*)d_in[1];
    const float* wgw   = (const float*)d_in[2];
    const float* wgf   = (const float*)d_in[3];
    const float* gamma = (const float*)d_in[4];
    const float* beta  = (const float*)d_in[5];
    const float* mean  = (const float*)d_in[6];
    const float* var   = (const float*)d_in[7];
    const float* wconv = (const float*)d_in[8];
    const float* bconv = (const float*)d_in[9];
    float* out = (float*)d_out;

    squeeze_kernel<<<BATCH * 128, 256>>>(x, wsq, out, wgf, gamma, beta, mean, var, wgw, wconv);
    carafe_kernel<<<512, 256>>>(bconv, out);
}

// round 13
// speedup vs baseline: 2.1349x; 1.3169x over previous
#include <cuda_runtime.h>
#include <cuda_bf16.h>
#include <cstdint>

#define BATCH 8
#define HWPIX 16384
#define CINC 66
#define TT 9
#define NCH 594
#define SMALLC 112
#define A_STRIDE 20   // fp32 words per A row (80B)

// ---------------- static device scratch ----------------
__device__ float    g_up[BATCH * 64 * HWPIX];   // squeeze up-channels (32 MB)
__device__ unsigned g_wbf[CINC * 1024];         // carafe fragment-major bf16 B
__device__ unsigned g_wbsq[32768];              // squeeze fragment-major bf16 B (hi/lo parts)
__device__ float    g_small[CINC * SMALLC];

// ---------------- helpers ----------------
__device__ __forceinline__ void ffma2(float2& acc, float2 a, float2 b) {
    asm("fma.rn.f32x2 %0, %1, %2, %0;"
        : "+l"(reinterpret_cast<unsigned long long&>(acc))
        : "l"(reinterpret_cast<unsigned long long const&>(a)),
          "l"(reinterpret_cast<unsigned long long const&>(b)));
}
__device__ __forceinline__ float fexp2p(float y) {
    y = fminf(fmaxf(y, -120.f), 120.f);
    float fl = floorf(y);
    float r = y - fl;
    float p = 1.33335581e-3f;
    p = fmaf(p, r, 9.61812911e-3f);
    p = fmaf(p, r, 5.55041087e-2f);
    p = fmaf(p, r, 2.40226507e-1f);
    p = fmaf(p, r, 6.93147181e-1f);
    p = fmaf(p, r, 1.0f);
    return p * __int_as_float(((int)fl + 127) << 23);
}
__device__ __forceinline__ unsigned short bfbits(float v) {
    __nv_bfloat16 h = __float2bfloat16(v);
    return *reinterpret_cast<unsigned short*>(&h);
}
__device__ __forceinline__ float bf2f(unsigned short u) {
    __nv_bfloat16 h = *reinterpret_cast<__nv_bfloat16*>(&u);
    return __bfloat162float(h);
}
__device__ __forceinline__ unsigned pack2(unsigned short a, unsigned short b) {
    return (unsigned)a | ((unsigned)b << 16);
}
__device__ __forceinline__ unsigned smem_u32(const void* p) {
    unsigned a; asm("{ .reg .u64 t; cvta.to.shared.u64 t, %1; cvt.u32.u64 %0, t; }" : "=r"(a) : "l"(p));
    return a;
}
__device__ __forceinline__ void mma_bf16(float* d, unsigned a0, unsigned a1,
                                         unsigned a2, unsigned a3,
                                         unsigned b0, unsigned b1) {
    asm volatile("mma.sync.aligned.m16n8k16.row.col.f32.bf16.bf16.f32 "
        "{%0,%1,%2,%3}, {%4,%5,%6,%7}, {%8,%9}, {%0,%1,%2,%3};"
        : "+f"(d[0]), "+f"(d[1]), "+f"(d[2]), "+f"(d[3])
        : "r"(a0), "r"(a1), "r"(a2), "r"(a3), "r"(b0), "r"(b1));
}
__device__ __forceinline__ void ldsm4(unsigned& r0, unsigned& r1, unsigned& r2, unsigned& r3,
                                      unsigned addr) {
    asm volatile("ldmatrix.sync.aligned.m8n8.x4.shared.b16 {%0,%1,%2,%3}, [%4];"
        : "=r"(r0), "=r"(r1), "=r"(r2), "=r"(r3) : "r"(addr));
}

// carafe B element (verified R8): K slots 0-8 hi(w), 9-17 hi(w), 18-26 lo(w), 27-31 zero
__device__ __forceinline__ unsigned short wb_elem(const float* __restrict__ wconv,
                                                  int c, int col, int k) {
    if (k >= 27) return 0;
    int t = (k < 9) ? k : (k < 18 ? k - 9 : k - 18);
    float wv = wconv[col * NCH + c * 9 + t];
    unsigned short hi = bfbits(wv);
    if (k < 18) return hi;
    return bfbits(wv - bf2f(hi));
}

// ================= K0: prep =================
__global__ void prep_kernel(const float* __restrict__ wsq, const float* __restrict__ gf,
                            const float* __restrict__ gamma, const float* __restrict__ beta,
                            const float* __restrict__ mean, const float* __restrict__ var,
                            const float* __restrict__ gw, const float* __restrict__ wconv) {
    int idx = blockIdx.x * 256 + threadIdx.x;
    if (idx < 32768) {
        // g_wbsq layout: ((kc*2+p)*32 + lane)*32 + nt*2 + reg
        int reg = idx & 1, nt = (idx >> 1) & 15, lane = (idx >> 5) & 31;
        int pc = idx >> 10, p = pc & 1, kc = pc >> 1;
        int col = nt * 8 + (lane >> 2);
        int k0 = kc * 16 + (lane & 3) * 2 + reg * 8;
        float w0 = wsq[col * 256 + k0], w1 = wsq[col * 256 + k0 + 1];
        unsigned short e0, e1;
        if (p == 0) { e0 = bfbits(w0); e1 = bfbits(w1); }
        else {
            e0 = bfbits(w0 - bf2f(bfbits(w0)));
            e1 = bfbits(w1 - bf2f(bfbits(w1)));
        }
        g_wbsq[idx] = pack2(e0, e1);
    } else if (idx < 32768 + CINC * 1024) {
        int i2 = idx - 32768;
        int c = i2 >> 10, r = i2 & 1023;
        int chunk = r >> 9;
        int lane2 = (r >> 4) & 31;
        int id = r & 15;
        int ntile = id >> 1, reg = id & 1;
        int gid2 = lane2 >> 2, tig2 = lane2 & 3;
        int col = ntile * 8 + gid2;
        int k0 = chunk * 16 + tig2 * 2 + reg * 8;
        g_wbf[i2] = pack2(wb_elem(wconv, c, col, k0), wb_elem(wconv, c, col, k0 + 1));
    } else if (idx < 32768 + CINC * 1024 + CINC * SMALLC) {
        int i3 = idx - (32768 + CINC * 1024);
        int c = i3 / SMALLC, s = i3 - c * SMALLC;
        float v = 0.f;
        if (s < 90) {
            int q = s >> 1, lane = s & 1;
            int u = q / 5, tp = q - u * 5, t = 2 * tp + lane;
            if (t < 9) {
                int i = c * 9 + t;
                float sc = gamma[i] * rsqrtf(var[i] + 1e-5f);
                v = gf[i * 9 + u] * sc;
            }
        } else if (s < 100) {
            int t = s - 90;
            if (t < 9) {
                int i = c * 9 + t;
                float sc = gamma[i] * rsqrtf(var[i] + 1e-5f);
                v = beta[i] - mean[i] * sc;
            }
        } else if (s < 109) {
            v = gw[c * 9 + (s - 100)] * 0.160299448987663f;  // log2(e)/9
        }
        g_small[i3] = v;
    }
}

// ================= K1: space-to-depth + 1x1 squeeze, mma.sync bf16 =================
// Block = (b,h): M=128 px, N=128 ch, K=256 (16 chunks of 16). 8 warps: mg=w&1 (64px), ng=w>>1 (32n).
__global__ __launch_bounds__(256, 2) void squeeze_kernel(
    const float* __restrict__ x, float* __restrict__ out) {
    __shared__ __align__(16) char sm[38144];   // A bufs 2x10240B; epilogue smT 64x140x4

    int tid = threadIdx.x;
    int lane = tid & 31, w = tid >> 5;
    int gid = lane >> 2, tig = lane & 3;
    int mg = w & 1, ng = w >> 1;
    int bid = blockIdx.x;
    int b = bid >> 7, h = bid & 127;
    const float* xb = x + (size_t)b * 64 * 65536;

    float acc[4][4][4];
    #pragma unroll
    for (int i = 0; i < 4; i++)
        #pragma unroll
        for (int j = 0; j < 4; j++)
            #pragma unroll
            for (int k = 0; k < 4; k++) acc[i][j][k] = 0.f;

    int px = tid & 127, khalf = tid >> 7;
    unsigned smbase = smem_u32(sm);
    const uint4* wb = (const uint4*)g_wbsq;

    float xv[8];
    // gather chunk kc raw x values
    #define GATHER(kc) do {                                                       \
        int kb = (kc) * 16 + khalf * 8;                                           \
        int q = kb >> 6, ci0 = kb & 63;                                           \
        const float* base = xb + (size_t)ci0 * 65536 +                            \
                            (2 * h + (q & 1)) * 256 + 2 * px + (q >> 1);          \
        _Pragma("unroll")                                                         \
        for (int i = 0; i < 8; i++) xv[i] = base[i * 65536];                      \
    } while (0)
    // convert + STS into buffer bu
    #define CVTSTS(bu) do {                                                       \
        unsigned short hb[8], lb[8];                                              \
        _Pragma("unroll")                                                         \
        for (int i = 0; i < 8; i++) {                                             \
            hb[i] = bfbits(xv[i]);                                                \
            lb[i] = bfbits(xv[i] - bf2f(hb[i]));                                  \
        }                                                                         \
        char* rp = sm + (bu) * 10240 + px * 80;                                   \
        *(uint4*)(rp + khalf * 16) = make_uint4(pack2(hb[0], hb[1]),              \
            pack2(hb[2], hb[3]), pack2(hb[4], hb[5]), pack2(hb[6], hb[7]));       \
        *(uint4*)(rp + 32 + khalf * 16) = make_uint4(pack2(lb[0], lb[1]),         \
            pack2(lb[2], lb[3]), pack2(lb[4], lb[5]), pack2(lb[6], lb[7]));       \
    } while (0)
    #define BIDX(kc, p) ((((kc) * 2 + (p)) * 32 + lane) * 8 + ng * 2)

    uint4 BH0, BH1, BL0, BL1, NH0, NH1, NL0, NL1;
    GATHER(0);
    BH0 = wb[BIDX(0, 0)]; BH1 = wb[BIDX(0, 0) + 1];
    BL0 = wb[BIDX(0, 1)]; BL1 = wb[BIDX(0, 1) + 1];
    CVTSTS(0);
    __syncthreads();

    for (int kc = 0; kc < 16; kc++) {
        int cur = kc & 1;
        bool more = kc < 15;
        if (more) {
            GATHER(kc + 1);
            NH0 = wb[BIDX(kc + 1, 0)]; NH1 = wb[BIDX(kc + 1, 0) + 1];
            NL0 = wb[BIDX(kc + 1, 1)]; NL1 = wb[BIDX(kc + 1, 1) + 1];
        }
        // ---- mma on cur buffer ----
        unsigned bh[8] = {BH0.x, BH0.y, BH0.z, BH0.w, BH1.x, BH1.y, BH1.z, BH1.w};
        unsigned bl[8] = {BL0.x, BL0.y, BL0.z, BL0.w, BL1.x, BL1.y, BL1.z, BL1.w};
        unsigned arow = smbase + cur * 10240 + (mg * 64 + (lane & 15)) * 80 + ((lane >> 4) * 16);
        #pragma unroll
        for (int mt = 0; mt < 4; mt++) {
            unsigned addr = arow + mt * (16 * 80);
            unsigned a0, a1, a2, a3, l0, l1, l2, l3;
            ldsm4(a0, a1, a2, a3, addr);
            ldsm4(l0, l1, l2, l3, addr + 32);
            #pragma unroll
            for (int nt = 0; nt < 4; nt++) {
                mma_bf16(acc[mt][nt], a0, a1, a2, a3, bh[nt * 2], bh[nt * 2 + 1]);
                mma_bf16(acc[mt][nt], l0, l1, l2, l3, bh[nt * 2], bh[nt * 2 + 1]);
                mma_bf16(acc[mt][nt], a0, a1, a2, a3, bl[nt * 2], bl[nt * 2 + 1]);
            }
        }
        if (more) {
            CVTSTS(cur ^ 1);
            BH0 = NH0; BH1 = NH1; BL0 = NL0; BL1 = NL1;
        }
        __syncthreads();
    }

    // ---- epilogue: smem transpose (stride 140, px-chunk skew 36; both %4==0 -> aligned LDS.128) ----
    float* smT = (float*)sm;
    #pragma unroll
    for (int pass = 0; pass < 2; pass++) {
        if (pass) __syncthreads();
        if ((ng >> 1) == pass) {
            #pragma unroll
            for (int mt = 0; mt < 4; mt++) {
                #pragma unroll
                for (int nt = 0; nt < 4; nt++) {
                    int col = (ng & 1) * 32 + nt * 8 + tig * 2;
                    int p0 = mg * 64 + mt * 16 + gid;
                    int pb0 = (p0 >> 5) * 36 + (p0 & 31);
                    int pb1 = ((p0 + 8) >> 5) * 36 + ((p0 + 8) & 31);
                    smT[col * 140 + pb0]       = acc[mt][nt][0];
                    smT[(col + 1) * 140 + pb0] = acc[mt][nt][1];
                    smT[col * 140 + pb1]       = acc[mt][nt][2];
                    smT[(col + 1) * 140 + pb1] = acc[mt][nt][3];
                }
            }
        }
        __syncthreads();
        // warp w owns cols {w, w+8, ...}: lanes sweep px (fully coalesced STG.128)
        int pxq = lane * 4;
        #pragma unroll
        for (int cc = 0; cc < 8; cc++) {
            int col = w + cc * 8;
            int co = pass * 64 + col;
            const float* src = smT + col * 140 + (pxq >> 5) * 36 + (pxq & 31);
            float4 v = *(const float4*)src;
            float* dst;
            if (co < 64) {
                dst = g_up + ((b * 64 + co) << 14) + h * 128 + pxq;
            } else {
                int l = co - 64;
                int oc = (l & 1) ? (96 + (l >> 1)) : (32 + (l >> 1));
                dst = out + ((b * 128 + oc) << 14) + h * 128 + pxq;
            }
            *(float4*)dst = v;
        }
    }
    #undef GATHER
    #undef CVTSTS
    #undef BIDX
}

// ================= K2: fused CARAFE tail, mma.sync bf16 (ldmatrix A) =================
__device__ __forceinline__ float rowval(const float* __restrict__ upb, int c, int gy, int gx) {
    if ((unsigned)gy >= 128u || (unsigned)gx >= 128u) return 0.f;
    if (c < 64) return upb[c * HWPIX + gy * 128 + gx];
    if (c == 64) return (float)gx * (2.0f / 127.0f) - 1.0f;
    return (float)gy * (2.0f / 127.0f) - 1.0f;
}

__global__ __launch_bounds__(256, 2) void carafe_kernel(
    const float* __restrict__ bconv, float* __restrict__ out) {
    __shared__ float smA[2 * 256 * A_STRIDE];   // 40960 B (also epilogue transpose buf)
    __shared__ float smRows[2 * 4 * 132];
    __shared__ float smSmall[2 * SMALLC];
    __shared__ float smBias[64];

    int tid = threadIdx.x;
    int lane = tid & 31, w = tid >> 5;
    int gid = lane >> 2, tig = lane & 3;
    int mg = w & 3, ng = w >> 2;
    int bidx = blockIdx.x;
    int b = bidx >> 6;
    int gy0 = (bidx & 63) * 2;
    int row = tid >> 7, gx = tid & 127;
    const float* upb = g_up + b * 64 * HWPIX;

    float acc[4][4][4];
    #pragma unroll
    for (int i = 0; i < 4; i++)
        #pragma unroll
        for (int j = 0; j < 4; j++)
            #pragma unroll
            for (int k = 0; k < 4; k++) acc[i][j][k] = 0.f;

    for (int i = tid; i < 520; i += 256) {
        int r = i / 130, col = i - r * 130;
        smRows[r * 132 + col] = rowval(upb, 0, gy0 - 1 + r, col - 1);
    }
    if (tid < SMALLC) smSmall[tid] = g_small[tid];
    if (tid < 64) smBias[tid] = bconv[tid];
    __syncthreads();

    for (int c = 0; c < CINC; c++) {
        int cb = c & 1, nb2 = cb ^ 1, c1 = c + 1;

        const uint4* wbp = (const uint4*)(g_wbf + c * 1024);
        int boff = (lane * 16 + ng * 8) >> 2;
        uint4 b00 = wbp[boff];
        uint4 b01 = wbp[boff + 1];
        uint4 b10 = wbp[boff + 128];
        uint4 b11 = wbp[boff + 129];

        float rt[3] = {0.f, 0.f, 0.f};
        float rs = 0.f;
        if (c1 < CINC) {
            #pragma unroll
            for (int j = 0; j < 3; j++) {
                int i = tid + j * 256;
                if (i < 520) {
                    int r = i / 130, col = i - r * 130;
                    rt[j] = rowval(upb, c1, gy0 - 1 + r, col - 1);
                }
            }
            if (tid < SMALLC) rs = g_small[c1 * SMALLC + tid];
        }

        // ---- phaseA: per-pixel sv[9] -> bf16 hi/lo packed A row ----
        unsigned u[16];
        {
            const float* rows = smRows + cb * 528;
            const float* smp  = smSmall + cb * SMALLC;
            float nbv[9];
            #pragma unroll
            for (int dy = 0; dy < 3; dy++)
                #pragma unroll
                for (int dx = 0; dx < 3; dx++)
                    nbv[dy * 3 + dx] = rows[(row + dy) * 132 + gx + dx];

            float rawsum = (((nbv[0] + nbv[1]) + (nbv[2] + nbv[3])) +
                            ((nbv[4] + nbv[5]) + (nbv[6] + nbv[7])) + nbv[8]);
            float e[9], esum = 0.f;
            #pragma unroll
            for (int t = 0; t < 9; t++) { e[t] = fexp2p(rawsum * smp[100 + t]); esum += e[t]; }
            float inv = __fdividef(1.0f, esum);

            float2 f2[5];
            #pragma unroll
            for (int tp = 0; tp < 5; tp++) f2[tp] = *(const float2*)&smp[90 + 2 * tp];
            #pragma unroll
            for (int uu = 0; uu < 9; uu++) {
                float2 nd = make_float2(nbv[uu], nbv[uu]);
                const float2* gp = (const float2*)&smp[2 * (uu * 5)];
                #pragma unroll
                for (int tp = 0; tp < 5; tp++) ffma2(f2[tp], nd, gp[tp]);
            }
            unsigned short hb[9], lb[9];
            #pragma unroll
            for (int t = 0; t < 9; t++) {
                float f = (t & 1) ? f2[t >> 1].y : f2[t >> 1].x;
                f = fmaxf(f, 0.f);
                float sv = f * e[t] * inv;
                hb[t] = bfbits(sv);
                lb[t] = bfbits(sv - bf2f(hb[t]));
            }
            u[0] = pack2(hb[0], hb[1]); u[1] = pack2(hb[2], hb[3]);
            u[2] = pack2(hb[4], hb[5]); u[3] = pack2(hb[6], hb[7]);
            u[4] = pack2(hb[8], lb[0]); u[5] = pack2(lb[1], lb[2]);
            u[6] = pack2(lb[3], lb[4]); u[7] = pack2(lb[5], lb[6]);
            u[8] = pack2(lb[7], lb[8]);
            u[9] = u[0]; u[10] = u[1]; u[11] = u[2]; u[12] = u[3];
            u[13] = (unsigned)hb[8];
            u[14] = 0u; u[15] = 0u;
        }

        {
            uint4* ap = (uint4*)(smA + cb * (256 * A_STRIDE) + tid * A_STRIDE);
            ap[0] = make_uint4(u[0], u[1], u[2], u[3]);
            ap[1] = make_uint4(u[4], u[5], u[6], u[7]);
            ap[2] = make_uint4(u[8], u[9], u[10], u[11]);
            ap[3] = make_uint4(u[12], u[13], u[14], u[15]);
        }
        if (c1 < CINC) {
            float* rowsN = smRows + nb2 * 528;
            #pragma unroll
            for (int j = 0; j < 3; j++) {
                int i = tid + j * 256;
                if (i < 520) {
                    int r = i / 130, col = i - r * 130;
                    rowsN[r * 132 + col] = rt[j];
                }
            }
            if (tid < SMALLC) smSmall[nb2 * SMALLC + tid] = rs;
        }
        __syncthreads();

        // ---- phaseB: mma with ldmatrix A-frag loads ----
        unsigned abase = smem_u32(smA) + cb * (256 * A_STRIDE * 4)
                       + (mg * 64 + (lane & 15)) * 80 + ((lane >> 4) * 16);
        #pragma unroll
        for (int chunk = 0; chunk < 2; chunk++) {
            unsigned breg[8];
            if (chunk == 0) {
                breg[0] = b00.x; breg[1] = b00.y; breg[2] = b00.z; breg[3] = b00.w;
                breg[4] = b01.x; breg[5] = b01.y; breg[6] = b01.z; breg[7] = b01.w;
            } else {
                breg[0] = b10.x; breg[1] = b10.y; breg[2] = b10.z; breg[3] = b10.w;
                breg[4] = b11.x; breg[5] = b11.y; breg[6] = b11.z; breg[7] = b11.w;
            }
            #pragma unroll
            for (int mt = 0; mt < 4; mt++) {
                unsigned a0, a1, a2, a3;
                ldsm4(a0, a1, a2, a3, abase + mt * (16 * 80) + chunk * 32);
                #pragma unroll
                for (int nt = 0; nt < 4; nt++)
                    mma_bf16(acc[mt][nt], a0, a1, a2, a3, breg[nt * 2], breg[nt * 2 + 1]);
            }
        }
    }

    // ---- epilogue (stride 288 / skew 36 — aligned, unchanged from R8) ----
    __syncthreads();
    float* trans = smA;
    #pragma unroll
    for (int pass = 0; pass < 2; pass++) {
        if (pass) __syncthreads();
        if (ng == pass) {
            #pragma unroll
            for (int mt = 0; mt < 4; mt++) {
                int px = mg * 64 + mt * 16 + gid;
                int pb = (px >> 5) * 36 + (px & 31);
                #pragma unroll
                for (int nt = 0; nt < 4; nt++) {
                    int nl = nt * 8 + tig * 2;
                    trans[nl * 288 + pb]           = acc[mt][nt][0];
                    trans[(nl + 1) * 288 + pb]     = acc[mt][nt][1];
                    trans[nl * 288 + pb + 8]       = acc[mt][nt][2];
                    trans[(nl + 1) * 288 + pb + 8] = acc[mt][nt][3];
                }
            }
        }
        __syncthreads();
        int nl = tid >> 3, k = tid & 7;
        int uch = pass * 32 + nl;
        int oc = (uch & 1) ? (64 + (uch >> 1)) : (uch >> 1);
        float bias = smBias[uch];
        const float* src = trans + nl * 288 + k * 36;
        float* dst = out + (b << 21) + (oc << 14) + gy0 * 128 + k * 32;
        #pragma unroll
        for (int j = 0; j < 8; j++) {
            float4 v = *(const float4*)(src + j * 4);
            v.x += bias; v.y += bias; v.z += bias; v.w += bias;
            *(float4*)(dst + j * 4) = v;
        }
    }
}

extern "C" void kernel_launch(void* const* d_in, const int* in_sizes, int n_in,
                              void* d_out, int out_size) {
    const float* x     = (const float*)d_in[0];
    const float* wsq   = (const float*)d_in[1];
    const float* wgw   = (const float*)d_in[2];
    const float* wgf   = (const float*)d_in[3];
    const float* gamma = (const float*)d_in[4];
    const float* beta  = (const float*)d_in[5];
    const float* mean  = (const float*)d_in[6];
    const float* var   = (const float*)d_in[7];
    const float* wconv = (const float*)d_in[8];
    const float* bconv = (const float*)d_in[9];
    float* out = (float*)d_out;

    int prep_elems = 32768 + CINC * 1024 + CINC * SMALLC;
    prep_kernel<<<(prep_elems + 255) / 256, 256>>>(wsq, wgf, gamma, beta, mean, var, wgw, wconv);
    squeeze_kernel<<<BATCH * 128, 256>>>(x, out);
    carafe_kernel<<<512, 256>>>(bconv, out);
}

// round 14
// speedup vs baseline: 2.5164x; 1.1787x over previous
#include <cuda_runtime.h>
#include <cuda_bf16.h>
#include <cstdint>

#define BATCH 8
#define HWPIX 16384
#define CINC 66
#define TT 9
#define NCH 594
#define SMALLC 112
#define A_STRIDE 20   // fp32 words per A row (80B)

// ---------------- static device scratch ----------------
__device__ float    g_up[BATCH * 64 * HWPIX];   // squeeze up-channels (32 MB)
__device__ unsigned g_wbf[CINC * 1024];         // carafe fragment-major bf16 B
__device__ unsigned g_wbsq[32768];              // squeeze fragment-major bf16 B (hi/lo parts)
__device__ float    g_small[CINC * SMALLC];

// ---------------- helpers ----------------
__device__ __forceinline__ void ffma2(float2& acc, float2 a, float2 b) {
    asm("fma.rn.f32x2 %0, %1, %2, %0;"
        : "+l"(reinterpret_cast<unsigned long long&>(acc))
        : "l"(reinterpret_cast<unsigned long long const&>(a)),
          "l"(reinterpret_cast<unsigned long long const&>(b)));
}
__device__ __forceinline__ float fexp2p(float y) {
    y = fminf(fmaxf(y, -120.f), 120.f);
    float fl = floorf(y);
    float r = y - fl;
    float p = 1.33335581e-3f;
    p = fmaf(p, r, 9.61812911e-3f);
    p = fmaf(p, r, 5.55041087e-2f);
    p = fmaf(p, r, 2.40226507e-1f);
    p = fmaf(p, r, 6.93147181e-1f);
    p = fmaf(p, r, 1.0f);
    return p * __int_as_float(((int)fl + 127) << 23);
}
__device__ __forceinline__ unsigned short bfbits(float v) {
    __nv_bfloat16 h = __float2bfloat16(v);
    return *reinterpret_cast<unsigned short*>(&h);
}
__device__ __forceinline__ float bf2f(unsigned short u) {
    __nv_bfloat16 h = *reinterpret_cast<__nv_bfloat16*>(&u);
    return __bfloat162float(h);
}
__device__ __forceinline__ unsigned pack2(unsigned short a, unsigned short b) {
    return (unsigned)a | ((unsigned)b << 16);
}
__device__ __forceinline__ unsigned smem_u32(const void* p) {
    unsigned a; asm("{ .reg .u64 t; cvta.to.shared.u64 t, %1; cvt.u32.u64 %0, t; }" : "=r"(a) : "l"(p));
    return a;
}
__device__ __forceinline__ void mma_bf16(float* d, unsigned a0, unsigned a1,
                                         unsigned a2, unsigned a3,
                                         unsigned b0, unsigned b1) {
    asm volatile("mma.sync.aligned.m16n8k16.row.col.f32.bf16.bf16.f32 "
        "{%0,%1,%2,%3}, {%4,%5,%6,%7}, {%8,%9}, {%0,%1,%2,%3};"
        : "+f"(d[0]), "+f"(d[1]), "+f"(d[2]), "+f"(d[3])
        : "r"(a0), "r"(a1), "r"(a2), "r"(a3), "r"(b0), "r"(b1));
}
__device__ __forceinline__ void ldsm4(unsigned& r0, unsigned& r1, unsigned& r2, unsigned& r3,
                                      unsigned addr) {
    asm volatile("ldmatrix.sync.aligned.m8n8.x4.shared.b16 {%0,%1,%2,%3}, [%4];"
        : "=r"(r0), "=r"(r1), "=r"(r2), "=r"(r3) : "r"(addr));
}

// carafe B element (verified R8): K slots 0-8 hi(w), 9-17 hi(w), 18-26 lo(w), 27-31 zero
__device__ __forceinline__ unsigned short wb_elem(const float* __restrict__ wconv,
                                                  int c, int col, int k) {
    if (k >= 27) return 0;
    int t = (k < 9) ? k : (k < 18 ? k - 9 : k - 18);
    float wv = wconv[col * NCH + c * 9 + t];
    unsigned short hi = bfbits(wv);
    if (k < 18) return hi;
    return bfbits(wv - bf2f(hi));
}

// ================= K0: prep (unchanged from R13) =================
__global__ void prep_kernel(const float* __restrict__ wsq, const float* __restrict__ gf,
                            const float* __restrict__ gamma, const float* __restrict__ beta,
                            const float* __restrict__ mean, const float* __restrict__ var,
                            const float* __restrict__ gw, const float* __restrict__ wconv) {
    int idx = blockIdx.x * 256 + threadIdx.x;
    if (idx < 32768) {
        int reg = idx & 1, nt = (idx >> 1) & 15, lane = (idx >> 5) & 31;
        int pc = idx >> 10, p = pc & 1, kc = pc >> 1;
        int col = nt * 8 + (lane >> 2);
        int k0 = kc * 16 + (lane & 3) * 2 + reg * 8;
        float w0 = wsq[col * 256 + k0], w1 = wsq[col * 256 + k0 + 1];
        unsigned short e0, e1;
        if (p == 0) { e0 = bfbits(w0); e1 = bfbits(w1); }
        else {
            e0 = bfbits(w0 - bf2f(bfbits(w0)));
            e1 = bfbits(w1 - bf2f(bfbits(w1)));
        }
        g_wbsq[idx] = pack2(e0, e1);
    } else if (idx < 32768 + CINC * 1024) {
        int i2 = idx - 32768;
        int c = i2 >> 10, r = i2 & 1023;
        int chunk = r >> 9;
        int lane2 = (r >> 4) & 31;
        int id = r & 15;
        int ntile = id >> 1, reg = id & 1;
        int gid2 = lane2 >> 2, tig2 = lane2 & 3;
        int col = ntile * 8 + gid2;
        int k0 = chunk * 16 + tig2 * 2 + reg * 8;
        g_wbf[i2] = pack2(wb_elem(wconv, c, col, k0), wb_elem(wconv, c, col, k0 + 1));
    } else if (idx < 32768 + CINC * 1024 + CINC * SMALLC) {
        int i3 = idx - (32768 + CINC * 1024);
        int c = i3 / SMALLC, s = i3 - c * SMALLC;
        float v = 0.f;
        if (s < 90) {
            int q = s >> 1, lane = s & 1;
            int u = q / 5, tp = q - u * 5, t = 2 * tp + lane;
            if (t < 9) {
                int i = c * 9 + t;
                float sc = gamma[i] * rsqrtf(var[i] + 1e-5f);
                v = gf[i * 9 + u] * sc;
            }
        } else if (s < 100) {
            int t = s - 90;
            if (t < 9) {
                int i = c * 9 + t;
                float sc = gamma[i] * rsqrtf(var[i] + 1e-5f);
                v = beta[i] - mean[i] * sc;
            }
        } else if (s < 109) {
            v = gw[c * 9 + (s - 100)] * 0.160299448987663f;  // log2(e)/9
        }
        g_small[i3] = v;
    }
}

// ================= K1: squeeze (unchanged from R13) =================
__global__ __launch_bounds__(256, 2) void squeeze_kernel(
    const float* __restrict__ x, float* __restrict__ out) {
    __shared__ __align__(16) char sm[38144];

    int tid = threadIdx.x;
    int lane = tid & 31, w = tid >> 5;
    int gid = lane >> 2, tig = lane & 3;
    int mg = w & 1, ng = w >> 1;
    int bid = blockIdx.x;
    int b = bid >> 7, h = bid & 127;
    const float* xb = x + (size_t)b * 64 * 65536;

    float acc[4][4][4];
    #pragma unroll
    for (int i = 0; i < 4; i++)
        #pragma unroll
        for (int j = 0; j < 4; j++)
            #pragma unroll
            for (int k = 0; k < 4; k++) acc[i][j][k] = 0.f;

    int px = tid & 127, khalf = tid >> 7;
    unsigned smbase = smem_u32(sm);
    const uint4* wb = (const uint4*)g_wbsq;

    float xv[8];
    #define GATHER(kc) do {                                                       \
        int kb = (kc) * 16 + khalf * 8;                                           \
        int q = kb >> 6, ci0 = kb & 63;                                           \
        const float* base = xb + (size_t)ci0 * 65536 +                            \
                            (2 * h + (q & 1)) * 256 + 2 * px + (q >> 1);          \
        _Pragma("unroll")                                                         \
        for (int i = 0; i < 8; i++) xv[i] = base[i * 65536];                      \
    } while (0)
    #define CVTSTS(bu) do {                                                       \
        unsigned short hb[8], lb[8];                                              \
        _Pragma("unroll")                                                         \
        for (int i = 0; i < 8; i++) {                                             \
            hb[i] = bfbits(xv[i]);                                                \
            lb[i] = bfbits(xv[i] - bf2f(hb[i]));                                  \
        }                                                                         \
        char* rp = sm + (bu) * 10240 + px * 80;                                   \
        *(uint4*)(rp + khalf * 16) = make_uint4(pack2(hb[0], hb[1]),              \
            pack2(hb[2], hb[3]), pack2(hb[4], hb[5]), pack2(hb[6], hb[7]));       \
        *(uint4*)(rp + 32 + khalf * 16) = make_uint4(pack2(lb[0], lb[1]),         \
            pack2(lb[2], lb[3]), pack2(lb[4], lb[5]), pack2(lb[6], lb[7]));       \
    } while (0)
    #define BIDX(kc, p) ((((kc) * 2 + (p)) * 32 + lane) * 8 + ng * 2)

    uint4 BH0, BH1, BL0, BL1, NH0, NH1, NL0, NL1;
    GATHER(0);
    BH0 = wb[BIDX(0, 0)]; BH1 = wb[BIDX(0, 0) + 1];
    BL0 = wb[BIDX(0, 1)]; BL1 = wb[BIDX(0, 1) + 1];
    CVTSTS(0);
    __syncthreads();

    for (int kc = 0; kc < 16; kc++) {
        int cur = kc & 1;
        bool more = kc < 15;
        if (more) {
            GATHER(kc + 1);
            NH0 = wb[BIDX(kc + 1, 0)]; NH1 = wb[BIDX(kc + 1, 0) + 1];
            NL0 = wb[BIDX(kc + 1, 1)]; NL1 = wb[BIDX(kc + 1, 1) + 1];
        }
        unsigned bh[8] = {BH0.x, BH0.y, BH0.z, BH0.w, BH1.x, BH1.y, BH1.z, BH1.w};
        unsigned bl[8] = {BL0.x, BL0.y, BL0.z, BL0.w, BL1.x, BL1.y, BL1.z, BL1.w};
        unsigned arow = smbase + cur * 10240 + (mg * 64 + (lane & 15)) * 80 + ((lane >> 4) * 16);
        #pragma unroll
        for (int mt = 0; mt < 4; mt++) {
            unsigned addr = arow + mt * (16 * 80);
            unsigned a0, a1, a2, a3, l0, l1, l2, l3;
            ldsm4(a0, a1, a2, a3, addr);
            ldsm4(l0, l1, l2, l3, addr + 32);
            #pragma unroll
            for (int nt = 0; nt < 4; nt++) {
                mma_bf16(acc[mt][nt], a0, a1, a2, a3, bh[nt * 2], bh[nt * 2 + 1]);
                mma_bf16(acc[mt][nt], l0, l1, l2, l3, bh[nt * 2], bh[nt * 2 + 1]);
                mma_bf16(acc[mt][nt], a0, a1, a2, a3, bl[nt * 2], bl[nt * 2 + 1]);
            }
        }
        if (more) {
            CVTSTS(cur ^ 1);
            BH0 = NH0; BH1 = NH1; BL0 = NL0; BL1 = NL1;
        }
        __syncthreads();
    }

    float* smT = (float*)sm;
    #pragma unroll
    for (int pass = 0; pass < 2; pass++) {
        if (pass) __syncthreads();
        if ((ng >> 1) == pass) {
            #pragma unroll
            for (int mt = 0; mt < 4; mt++) {
                #pragma unroll
                for (int nt = 0; nt < 4; nt++) {
                    int col = (ng & 1) * 32 + nt * 8 + tig * 2;
                    int p0 = mg * 64 + mt * 16 + gid;
                    int pb0 = (p0 >> 5) * 36 + (p0 & 31);
                    int pb1 = ((p0 + 8) >> 5) * 36 + ((p0 + 8) & 31);
                    smT[col * 140 + pb0]       = acc[mt][nt][0];
                    smT[(col + 1) * 140 + pb0] = acc[mt][nt][1];
                    smT[col * 140 + pb1]       = acc[mt][nt][2];
                    smT[(col + 1) * 140 + pb1] = acc[mt][nt][3];
                }
            }
        }
        __syncthreads();
        int pxq = lane * 4;
        #pragma unroll
        for (int cc = 0; cc < 8; cc++) {
            int col = w + cc * 8;
            int co = pass * 64 + col;
            const float* src = smT + col * 140 + (pxq >> 5) * 36 + (pxq & 31);
            float4 v = *(const float4*)src;
            float* dst;
            if (co < 64) {
                dst = g_up + ((b * 64 + co) << 14) + h * 128 + pxq;
            } else {
                int l = co - 64;
                int oc = (l & 1) ? (96 + (l >> 1)) : (32 + (l >> 1));
                dst = out + ((b * 128 + oc) << 14) + h * 128 + pxq;
            }
            *(float4*)dst = v;
        }
    }
    #undef GATHER
    #undef CVTSTS
    #undef BIDX
}

// ================= K2: carafe — rotated pipeline, 128-thread blocks =================
__device__ __forceinline__ float rowval(const float* __restrict__ upb, int c, int gy, int gx) {
    if ((unsigned)gy >= 128u || (unsigned)gx >= 128u) return 0.f;
    if (c < 64) return upb[c * HWPIX + gy * 128 + gx];
    if (c == 64) return (float)gx * (2.0f / 127.0f) - 1.0f;
    return (float)gy * (2.0f / 127.0f) - 1.0f;
}

// smem layout (bytes): A 2x128x80 @0 (20480) | rows 2x396f @20480 | small 2x112f @23648
//                      | (epilogue trans 64x132f overlays @0, 33792) | bias 64f @33792
#define CSM_TOTAL 34048
__global__ __launch_bounds__(128, 4) void carafe_kernel(
    const float* __restrict__ bconv, float* __restrict__ out) {
    __shared__ __align__(16) char smc[CSM_TOTAL];
    float* smA    = (float*)smc;
    float* smRows = (float*)(smc + 20480);
    float* smSmall= (float*)(smc + 23648);
    float* smBias = (float*)(smc + 33792);

    int tid = threadIdx.x;            // 0..127
    int lane = tid & 31, w = tid >> 5;
    int gid = lane >> 2, tig = lane & 3;
    int mg = w & 1, ng = w >> 1;
    int gy = blockIdx.x;
    int b  = blockIdx.y;
    int gx = tid;
    const float* upb = g_up + b * 64 * HWPIX;
    unsigned abase0 = smem_u32(smA) + (mg * 64 + (lane & 15)) * 80 + ((lane >> 4) * 16);

    float acc[4][4][4];
    #pragma unroll
    for (int i = 0; i < 4; i++)
        #pragma unroll
        for (int j = 0; j < 4; j++)
            #pragma unroll
            for (int k = 0; k < 4; k++) acc[i][j][k] = 0.f;

    // ---- phaseA body (channel data in buf cb) -> STS A[cb] ----
    #define PHASE_A(cb) do {                                                          \
        const float* rows = smRows + (cb) * 396;                                      \
        const float* smp  = smSmall + (cb) * SMALLC;                                  \
        float nbv[9];                                                                 \
        _Pragma("unroll")                                                             \
        for (int dy = 0; dy < 3; dy++)                                                \
            _Pragma("unroll")                                                         \
            for (int dx = 0; dx < 3; dx++)                                            \
                nbv[dy * 3 + dx] = rows[dy * 132 + gx + dx];                          \
        float rawsum = (((nbv[0] + nbv[1]) + (nbv[2] + nbv[3])) +                     \
                        ((nbv[4] + nbv[5]) + (nbv[6] + nbv[7])) + nbv[8]);            \
        float e[9], esum = 0.f;                                                       \
        _Pragma("unroll")                                                             \
        for (int t = 0; t < 9; t++) { e[t] = fexp2p(rawsum * smp[100 + t]); esum += e[t]; } \
        float inv = __fdividef(1.0f, esum);                                           \
        float2 f2[5];                                                                 \
        _Pragma("unroll")                                                             \
        for (int tp = 0; tp < 5; tp++) f2[tp] = *(const float2*)&smp[90 + 2 * tp];    \
        _Pragma("unroll")                                                             \
        for (int uu = 0; uu < 9; uu++) {                                              \
            float2 nd = make_float2(nbv[uu], nbv[uu]);                                \
            const float2* gp = (const float2*)&smp[2 * (uu * 5)];                     \
            _Pragma("unroll")                                                         \
            for (int tp = 0; tp < 5; tp++) ffma2(f2[tp], nd, gp[tp]);                 \
        }                                                                             \
        unsigned short hb[9], lb[9];                                                  \
        _Pragma("unroll")                                                             \
        for (int t = 0; t < 9; t++) {                                                 \
            float f = (t & 1) ? f2[t >> 1].y : f2[t >> 1].x;                          \
            f = fmaxf(f, 0.f);                                                        \
            float sv = f * e[t] * inv;                                                \
            hb[t] = bfbits(sv);                                                       \
            lb[t] = bfbits(sv - bf2f(hb[t]));                                         \
        }                                                                             \
        unsigned u0 = pack2(hb[0], hb[1]), u1 = pack2(hb[2], hb[3]);                  \
        unsigned u2 = pack2(hb[4], hb[5]), u3 = pack2(hb[6], hb[7]);                  \
        unsigned u4 = pack2(hb[8], lb[0]), u5 = pack2(lb[1], lb[2]);                  \
        unsigned u6 = pack2(lb[3], lb[4]), u7 = pack2(lb[5], lb[6]);                  \
        unsigned u8 = pack2(lb[7], lb[8]);                                            \
        uint4* ap = (uint4*)(smA + (cb) * (128 * A_STRIDE) + tid * A_STRIDE);         \
        ap[0] = make_uint4(u0, u1, u2, u3);                                           \
        ap[1] = make_uint4(u4, u5, u6, u7);                                           \
        ap[2] = make_uint4(u8, u0, u1, u2);                                           \
        ap[3] = make_uint4(u3, (unsigned)hb[8], 0u, 0u);                              \
    } while (0)

    // ---- preamble: stage c=0, bias; phaseA(0); stage c=1; load B(0) ----
    #pragma unroll
    for (int j = 0; j < 4; j++) {
        int i = tid + j * 128;
        if (i < 390) {
            int r = i / 130, col = i - r * 130;
            smRows[r * 132 + col] = rowval(upb, 0, gy - 1 + r, col - 1);
        }
    }
    if (tid < SMALLC) smSmall[tid] = g_small[tid];
    if (tid < 64) smBias[tid] = bconv[tid];
    __syncthreads();

    int boff = (lane * 16 + ng * 8) >> 2;
    const uint4* wbp = (const uint4*)g_wbf;
    uint4 b00 = wbp[boff], b01 = wbp[boff + 1], b10 = wbp[boff + 128], b11 = wbp[boff + 129];

    PHASE_A(0);
    #pragma unroll
    for (int j = 0; j < 4; j++) {
        int i = tid + j * 128;
        if (i < 390) {
            int r = i / 130, col = i - r * 130;
            smRows[396 + r * 132 + col] = rowval(upb, 1, gy - 1 + r, col - 1);
        }
    }
    if (tid < SMALLC) smSmall[SMALLC + tid] = g_small[SMALLC + tid];
    __syncthreads();

    // ---- main loop: iter c does phaseB(c-1) || phaseA(c) || prefetch(c+1) ----
    for (int c = 1; c < CINC; c++) {
        int pb = (c - 1) & 1, cb = c & 1;

        // prefetch rows/small for c+1 (independent LDGs, fly during mma+phaseA)
        float rt[4] = {0.f, 0.f, 0.f, 0.f};
        float rs = 0.f;
        if (c + 1 < CINC) {
            #pragma unroll
            for (int j = 0; j < 4; j++) {
                int i = tid + j * 128;
                if (i < 390) {
                    int r = i / 130, col = i - r * 130;
                    rt[j] = rowval(upb, c + 1, gy - 1 + r, col - 1);
                }
            }
            if (tid < SMALLC) rs = g_small[(c + 1) * SMALLC + tid];
        }

        // phaseB(c-1): mma from A[pb] with held B regs (B(c-1))
        {
            unsigned abase = abase0 + pb * (128 * A_STRIDE * 4);
            unsigned bh0[8] = {b00.x, b00.y, b00.z, b00.w, b01.x, b01.y, b01.z, b01.w};
            unsigned bh1[8] = {b10.x, b10.y, b10.z, b10.w, b11.x, b11.y, b11.z, b11.w};
            #pragma unroll
            for (int mt = 0; mt < 4; mt++) {
                unsigned a0, a1, a2, a3;
                ldsm4(a0, a1, a2, a3, abase + mt * (16 * 80));
                #pragma unroll
                for (int nt = 0; nt < 4; nt++)
                    mma_bf16(acc[mt][nt], a0, a1, a2, a3, bh0[nt * 2], bh0[nt * 2 + 1]);
                unsigned c0, c1r, c2, c3;
                ldsm4(c0, c1r, c2, c3, abase + mt * (16 * 80) + 32);
                #pragma unroll
                for (int nt = 0; nt < 4; nt++)
                    mma_bf16(acc[mt][nt], c0, c1r, c2, c3, bh1[nt * 2], bh1[nt * 2 + 1]);
            }
        }

        // load B(c) (after last read of B(c-1))
        wbp = (const uint4*)(g_wbf + c * 1024);
        b00 = wbp[boff]; b01 = wbp[boff + 1]; b10 = wbp[boff + 128]; b11 = wbp[boff + 129];

        // phaseA(c) + STS A[cb]
        PHASE_A(cb);

        // stage rows/small(c+1) into buf pb
        if (c + 1 < CINC) {
            #pragma unroll
            for (int j = 0; j < 4; j++) {
                int i = tid + j * 128;
                if (i < 390) {
                    int r = i / 130, col = i - r * 130;
                    smRows[pb * 396 + r * 132 + col] = rt[j];
                }
            }
            if (tid < SMALLC) smSmall[pb * SMALLC + tid] = rs;
        }
        __syncthreads();
    }

    // ---- final phaseB(65) ----
    {
        unsigned abase = abase0 + ((CINC - 1) & 1) * (128 * A_STRIDE * 4);
        unsigned bh0[8] = {b00.x, b00.y, b00.z, b00.w, b01.x, b01.y, b01.z, b01.w};
        unsigned bh1[8] = {b10.x, b10.y, b10.z, b10.w, b11.x, b11.y, b11.z, b11.w};
        #pragma unroll
        for (int mt = 0; mt < 4; mt++) {
            unsigned a0, a1, a2, a3;
            ldsm4(a0, a1, a2, a3, abase + mt * (16 * 80));
            #pragma unroll
            for (int nt = 0; nt < 4; nt++)
                mma_bf16(acc[mt][nt], a0, a1, a2, a3, bh0[nt * 2], bh0[nt * 2 + 1]);
            unsigned c0, c1r, c2, c3;
            ldsm4(c0, c1r, c2, c3, abase + mt * (16 * 80) + 32);
            #pragma unroll
            for (int nt = 0; nt < 4; nt++)
                mma_bf16(acc[mt][nt], c0, c1r, c2, c3, bh1[nt * 2], bh1[nt * 2 + 1]);
        }
    }
    __syncthreads();   // all ldsm reads of smA done before transpose overwrites

    // ---- epilogue: transpose via smem (stride 132), bias, channel shuffle ----
    float* trans = (float*)smc;
    #pragma unroll
    for (int mt = 0; mt < 4; mt++) {
        int px = mg * 64 + mt * 16 + gid;
        #pragma unroll
        for (int nt = 0; nt < 4; nt++) {
            int n = ng * 32 + nt * 8 + tig * 2;
            trans[n * 132 + px]           = acc[mt][nt][0];
            trans[(n + 1) * 132 + px]     = acc[mt][nt][1];
            trans[n * 132 + px + 8]       = acc[mt][nt][2];
            trans[(n + 1) * 132 + px + 8] = acc[mt][nt][3];
        }
    }
    __syncthreads();
    #pragma unroll
    for (int cc = 0; cc < 16; cc++) {
        int col = w * 16 + cc;          // up-channel 0..63
        int oc = (col & 1) ? (64 + (col >> 1)) : (col >> 1);
        float bias = smBias[col];
        float4 v = *(const float4*)(trans + col * 132 + lane * 4);
        v.x += bias; v.y += bias; v.z += bias; v.w += bias;
        *(float4*)(out + ((b * 128 + oc) << 14) + gy * 128 + lane * 4) = v;
    }
    #undef PHASE_A
}

extern "C" void kernel_launch(void* const* d_in, const int* in_sizes, int n_in,
                              void* d_out, int out_size) {
    const float* x     = (const float*)d_in[0];
    const float* wsq   = (const float*)d_in[1];
    const float* wgw   = (const float*)d_in[2];
    const float* wgf   = (const float*)d_in[3];
    const float* gamma = (const float*)d_in[4];
    const float* beta  = (const float*)d_in[5];
    const float* mean  = (const float*)d_in[6];
    const float* var   = (const float*)d_in[7];
    const float* wconv = (const float*)d_in[8];
    const float* bconv = (const float*)d_in[9];
    float* out = (float*)d_out;

    int prep_elems = 32768 + CINC * 1024 + CINC * SMALLC;
    prep_kernel<<<(prep_elems + 255) / 256, 256>>>(wsq, wgf, gamma, beta, mean, var, wgw, wconv);
    squeeze_kernel<<<BATCH * 128, 256>>>(x, out);
    carafe_kernel<<<dim3(128, BATCH), 128>>>(bconv, out);
}

// round 16
// speedup vs baseline: 2.5972x; 1.0321x over previous
#include <cuda_runtime.h>
#include <cuda_bf16.h>
#include <cstdint>

#define BATCH 8
#define HWPIX 16384
#define CINC 66
#define TT 9
#define NCH 594
#define SMALLC 112
#define A_STRIDE 20   // fp32 words per A row (80B)

// ---------------- static device scratch ----------------
__device__ float    g_up[BATCH * 64 * HWPIX];   // squeeze up-channels (32 MB)
__device__ unsigned g_wbf[CINC * 1024];         // carafe fragment-major bf16 B
__device__ unsigned g_wbsq[32768];              // squeeze fragment-major bf16 B (hi/lo parts)
__device__ float    g_small[CINC * SMALLC];

// ---------------- helpers ----------------
__device__ __forceinline__ void ffma2(float2& acc, float2 a, float2 b) {
    asm("fma.rn.f32x2 %0, %1, %2, %0;"
        : "+l"(reinterpret_cast<unsigned long long&>(acc))
        : "l"(reinterpret_cast<unsigned long long const&>(a)),
          "l"(reinterpret_cast<unsigned long long const&>(b)));
}
__device__ __forceinline__ float fexp2p(float y) {
    y = fminf(fmaxf(y, -120.f), 120.f);
    float fl = floorf(y);
    float r = y - fl;
    float p = 1.33335581e-3f;
    p = fmaf(p, r, 9.61812911e-3f);
    p = fmaf(p, r, 5.55041087e-2f);
    p = fmaf(p, r, 2.40226507e-1f);
    p = fmaf(p, r, 6.93147181e-1f);
    p = fmaf(p, r, 1.0f);
    return p * __int_as_float(((int)fl + 127) << 23);
}
__device__ __forceinline__ unsigned short bfbits(float v) {
    __nv_bfloat16 h = __float2bfloat16(v);
    return *reinterpret_cast<unsigned short*>(&h);
}
__device__ __forceinline__ float bf2f(unsigned short u) {
    __nv_bfloat16 h = *reinterpret_cast<__nv_bfloat16*>(&u);
    return __bfloat162float(h);
}
__device__ __forceinline__ unsigned pack2(unsigned short a, unsigned short b) {
    return (unsigned)a | ((unsigned)b << 16);
}
__device__ __forceinline__ unsigned smem_u32(const void* p) {
    unsigned a; asm("{ .reg .u64 t; cvta.to.shared.u64 t, %1; cvt.u32.u64 %0, t; }" : "=r"(a) : "l"(p));
    return a;
}
__device__ __forceinline__ void mma_bf16(float* d, unsigned a0, unsigned a1,
                                         unsigned a2, unsigned a3,
                                         unsigned b0, unsigned b1) {
    asm volatile("mma.sync.aligned.m16n8k16.row.col.f32.bf16.bf16.f32 "
        "{%0,%1,%2,%3}, {%4,%5,%6,%7}, {%8,%9}, {%0,%1,%2,%3};"
        : "+f"(d[0]), "+f"(d[1]), "+f"(d[2]), "+f"(d[3])
        : "r"(a0), "r"(a1), "r"(a2), "r"(a3), "r"(b0), "r"(b1));
}
__device__ __forceinline__ void ldsm4(unsigned& r0, unsigned& r1, unsigned& r2, unsigned& r3,
                                      unsigned addr) {
    asm volatile("ldmatrix.sync.aligned.m8n8.x4.shared.b16 {%0,%1,%2,%3}, [%4];"
        : "=r"(r0), "=r"(r1), "=r"(r2), "=r"(r3) : "r"(addr));
}

// carafe B element (verified R8): K slots 0-8 hi(w), 9-17 hi(w), 18-26 lo(w), 27-31 zero
__device__ __forceinline__ unsigned short wb_elem(const float* __restrict__ wconv,
                                                  int c, int col, int k) {
    if (k >= 27) return 0;
    int t = (k < 9) ? k : (k < 18 ? k - 9 : k - 18);
    float wv = wconv[col * NCH + c * 9 + t];
    unsigned short hi = bfbits(wv);
    if (k < 18) return hi;
    return bfbits(wv - bf2f(hi));
}

// ================= K0: prep (unchanged) =================
__global__ void prep_kernel(const float* __restrict__ wsq, const float* __restrict__ gf,
                            const float* __restrict__ gamma, const float* __restrict__ beta,
                            const float* __restrict__ mean, const float* __restrict__ var,
                            const float* __restrict__ gw, const float* __restrict__ wconv) {
    int idx = blockIdx.x * 256 + threadIdx.x;
    if (idx < 32768) {
        int reg = idx & 1, nt = (idx >> 1) & 15, lane = (idx >> 5) & 31;
        int pc = idx >> 10, p = pc & 1, kc = pc >> 1;
        int col = nt * 8 + (lane >> 2);
        int k0 = kc * 16 + (lane & 3) * 2 + reg * 8;
        float w0 = wsq[col * 256 + k0], w1 = wsq[col * 256 + k0 + 1];
        unsigned short e0, e1;
        if (p == 0) { e0 = bfbits(w0); e1 = bfbits(w1); }
        else {
            e0 = bfbits(w0 - bf2f(bfbits(w0)));
            e1 = bfbits(w1 - bf2f(bfbits(w1)));
        }
        g_wbsq[idx] = pack2(e0, e1);
    } else if (idx < 32768 + CINC * 1024) {
        int i2 = idx - 32768;
        int c = i2 >> 10, r = i2 & 1023;
        int chunk = r >> 9;
        int lane2 = (r >> 4) & 31;
        int id = r & 15;
        int ntile = id >> 1, reg = id & 1;
        int gid2 = lane2 >> 2, tig2 = lane2 & 3;
        int col = ntile * 8 + gid2;
        int k0 = chunk * 16 + tig2 * 2 + reg * 8;
        g_wbf[i2] = pack2(wb_elem(wconv, c, col, k0), wb_elem(wconv, c, col, k0 + 1));
    } else if (idx < 32768 + CINC * 1024 + CINC * SMALLC) {
        int i3 = idx - (32768 + CINC * 1024);
        int c = i3 / SMALLC, s = i3 - c * SMALLC;
        float v = 0.f;
        if (s < 90) {
            int q = s >> 1, lane = s & 1;
            int u = q / 5, tp = q - u * 5, t = 2 * tp + lane;
            if (t < 9) {
                int i = c * 9 + t;
                float sc = gamma[i] * rsqrtf(var[i] + 1e-5f);
                v = gf[i * 9 + u] * sc;
            }
        } else if (s < 100) {
            int t = s - 90;
            if (t < 9) {
                int i = c * 9 + t;
                float sc = gamma[i] * rsqrtf(var[i] + 1e-5f);
                v = beta[i] - mean[i] * sc;
            }
        } else if (s < 109) {
            v = gw[c * 9 + (s - 100)] * 0.160299448987663f;  // log2(e)/9
        }
        g_small[i3] = v;
    }
}

// ================= K1: squeeze — M=64 blocks, 128 threads, occ 4 =================
// Block = (b,h,half): M=64 px, N=128 ch, K=256 (16 chunks). 4 warps, warp = 64px x 32n.
__global__ __launch_bounds__(128, 4) void squeeze_kernel(
    const float* __restrict__ x, float* __restrict__ out) {
    __shared__ __align__(16) char sm[34816];   // A bufs 2x5120B; epilogue trans 128x68x4 overlay

    int tid = threadIdx.x;
    int lane = tid & 31, w = tid >> 5;   // w = ng (0..3)
    int ng = w;
    int bid = blockIdx.x;
    int b = bid >> 8;
    int h = (bid >> 1) & 127;
    int half = bid & 1;
    const float* xb = x + (size_t)b * 64 * 65536;

    float acc[4][4][4];
    #pragma unroll
    for (int i = 0; i < 4; i++)
        #pragma unroll
        for (int j = 0; j < 4; j++)
            #pragma unroll
            for (int k = 0; k < 4; k++) acc[i][j][k] = 0.f;

    int px = tid & 63, khalf = tid >> 6;
    int pxg = half * 64 + px;
    unsigned smbase = smem_u32(sm);
    const uint4* wb = (const uint4*)g_wbsq;

    float xv[8];
    #define GATHER(kc) do {                                                       \
        int kb = (kc) * 16 + khalf * 8;                                           \
        int q = kb >> 6, ci0 = kb & 63;                                           \
        const float* base = xb + (size_t)ci0 * 65536 +                            \
                            (2 * h + (q & 1)) * 256 + 2 * pxg + (q >> 1);         \
        _Pragma("unroll")                                                         \
        for (int i = 0; i < 8; i++) xv[i] = base[i * 65536];                      \
    } while (0)
    #define CVTSTS(bu) do {                                                       \
        unsigned short hb[8], lb[8];                                              \
        _Pragma("unroll")                                                         \
        for (int i = 0; i < 8; i++) {                                             \
            hb[i] = bfbits(xv[i]);                                                \
            lb[i] = bfbits(xv[i] - bf2f(hb[i]));                                  \
        }                                                                         \
        char* rp = sm + (bu) * 5120 + px * 80;                                    \
        *(uint4*)(rp + khalf * 16) = make_uint4(pack2(hb[0], hb[1]),              \
            pack2(hb[2], hb[3]), pack2(hb[4], hb[5]), pack2(hb[6], hb[7]));       \
        *(uint4*)(rp + 32 + khalf * 16) = make_uint4(pack2(lb[0], lb[1]),         \
            pack2(lb[2], lb[3]), pack2(lb[4], lb[5]), pack2(lb[6], lb[7]));       \
    } while (0)
    #define BIDX(kc, p) ((((kc) * 2 + (p)) * 32 + lane) * 8 + ng * 2)

    uint4 BH0, BH1, BL0, BL1, NH0, NH1, NL0, NL1;
    GATHER(0);
    BH0 = wb[BIDX(0, 0)]; BH1 = wb[BIDX(0, 0) + 1];
    BL0 = wb[BIDX(0, 1)]; BL1 = wb[BIDX(0, 1) + 1];
    CVTSTS(0);
    __syncthreads();

    for (int kc = 0; kc < 16; kc++) {
        int cur = kc & 1;
        bool more = kc < 15;
        if (more) {
            GATHER(kc + 1);
            NH0 = wb[BIDX(kc + 1, 0)]; NH1 = wb[BIDX(kc + 1, 0) + 1];
            NL0 = wb[BIDX(kc + 1, 1)]; NL1 = wb[BIDX(kc + 1, 1) + 1];
        }
        unsigned bh[8] = {BH0.x, BH0.y, BH0.z, BH0.w, BH1.x, BH1.y, BH1.z, BH1.w};
        unsigned bl[8] = {BL0.x, BL0.y, BL0.z, BL0.w, BL1.x, BL1.y, BL1.z, BL1.w};
        unsigned arow = smbase + cur * 5120 + (lane & 15) * 80 + ((lane >> 4) * 16);
        #pragma unroll
        for (int mt = 0; mt < 4; mt++) {
            unsigned addr = arow + mt * (16 * 80);
            unsigned a0, a1, a2, a3, l0, l1, l2, l3;
            ldsm4(a0, a1, a2, a3, addr);
            ldsm4(l0, l1, l2, l3, addr + 32);
            #pragma unroll
            for (int nt = 0; nt < 4; nt++) {
                mma_bf16(acc[mt][nt], a0, a1, a2, a3, bh[nt * 2], bh[nt * 2 + 1]);
                mma_bf16(acc[mt][nt], l0, l1, l2, l3, bh[nt * 2], bh[nt * 2 + 1]);
                mma_bf16(acc[mt][nt], a0, a1, a2, a3, bl[nt * 2], bl[nt * 2 + 1]);
            }
        }
        if (more) {
            CVTSTS(cur ^ 1);
            BH0 = NH0; BH1 = NH1; BL0 = NL0; BL1 = NL1;
        }
        __syncthreads();
    }

    // ---- epilogue: single-pass transpose, 128 cols x 64 px (stride 68) ----
    {
        float* trans = (float*)sm;
        int gid = lane >> 2, tig = lane & 3;
        #pragma unroll
        for (int mt = 0; mt < 4; mt++) {
            int p0 = mt * 16 + gid;
            #pragma unroll
            for (int nt = 0; nt < 4; nt++) {
                int col = ng * 32 + nt * 8 + tig * 2;
                trans[col * 68 + p0]           = acc[mt][nt][0];
                trans[(col + 1) * 68 + p0]     = acc[mt][nt][1];
                trans[col * 68 + p0 + 8]       = acc[mt][nt][2];
                trans[(col + 1) * 68 + p0 + 8] = acc[mt][nt][3];
            }
        }
        __syncthreads();
        int rowoff = h * 128 + half * 64 + lane * 2;
        #pragma unroll
        for (int cc = 0; cc < 32; cc++) {
            int co = w * 32 + cc;
            float2 v = *(const float2*)(trans + co * 68 + lane * 2);
            float* dst;
            if (co < 64) {
                dst = g_up + ((b * 64 + co) << 14) + rowoff;
            } else {
                int l = co - 64;
                int oc = (l & 1) ? (96 + (l >> 1)) : (32 + (l >> 1));
                dst = out + ((b * 128 + oc) << 14) + rowoff;
            }
            *(float2*)dst = v;
        }
    }
    #undef GATHER
    #undef CVTSTS
    #undef BIDX
}

// ================= K2: carafe (unchanged from R14) =================
__device__ __forceinline__ float rowval(const float* __restrict__ upb, int c, int gy, int gx) {
    if ((unsigned)gy >= 128u || (unsigned)gx >= 128u) return 0.f;
    if (c < 64) return upb[c * HWPIX + gy * 128 + gx];
    if (c == 64) return (float)gx * (2.0f / 127.0f) - 1.0f;
    return (float)gy * (2.0f / 127.0f) - 1.0f;
}

#define CSM_TOTAL 34048
__global__ __launch_bounds__(128, 4) void carafe_kernel(
    const float* __restrict__ bconv, float* __restrict__ out) {
    __shared__ __align__(16) char smc[CSM_TOTAL];
    float* smA    = (float*)smc;
    float* smRows = (float*)(smc + 20480);
    float* smSmall= (float*)(smc + 23648);
    float* smBias = (float*)(smc + 33792);

    int tid = threadIdx.x;
    int lane = tid & 31, w = tid >> 5;
    int gid = lane >> 2, tig = lane & 3;
    int mg = w & 1, ng = w >> 1;
    int gy = blockIdx.x;
    int b  = blockIdx.y;
    int gx = tid;
    const float* upb = g_up + b * 64 * HWPIX;
    unsigned abase0 = smem_u32(smA) + (mg * 64 + (lane & 15)) * 80 + ((lane >> 4) * 16);

    float acc[4][4][4];
    #pragma unroll
    for (int i = 0; i < 4; i++)
        #pragma unroll
        for (int j = 0; j < 4; j++)
            #pragma unroll
            for (int k = 0; k < 4; k++) acc[i][j][k] = 0.f;

    #define PHASE_A(cb) do {                                                          \
        const float* rows = smRows + (cb) * 396;                                      \
        const float* smp  = smSmall + (cb) * SMALLC;                                  \
        float nbv[9];                                                                 \
        _Pragma("unroll")                                                             \
        for (int dy = 0; dy < 3; dy++)                                                \
            _Pragma("unroll")                                                         \
            for (int dx = 0; dx < 3; dx++)                                            \
                nbv[dy * 3 + dx] = rows[dy * 132 + gx + dx];                          \
        float rawsum = (((nbv[0] + nbv[1]) + (nbv[2] + nbv[3])) +                     \
                        ((nbv[4] + nbv[5]) + (nbv[6] + nbv[7])) + nbv[8]);            \
        float e[9], esum = 0.f;                                                       \
        _Pragma("unroll")                                                             \
        for (int t = 0; t < 9; t++) { e[t] = fexp2p(rawsum * smp[100 + t]); esum += e[t]; } \
        float inv = __fdividef(1.0f, esum);                                           \
        float2 f2[5];                                                                 \
        _Pragma("unroll")                                                             \
        for (int tp = 0; tp < 5; tp++) f2[tp] = *(const float2*)&smp[90 + 2 * tp];    \
        _Pragma("unroll")                                                             \
        for (int uu = 0; uu < 9; uu++) {                                              \
            float2 nd = make_float2(nbv[uu], nbv[uu]);                                \
            const float2* gp = (const float2*)&smp[2 * (uu * 5)];                     \
            _Pragma("unroll")                                                         \
            for (int tp = 0; tp < 5; tp++) ffma2(f2[tp], nd, gp[tp]);                 \
        }                                                                             \
        unsigned short hb[9], lb[9];                                                  \
        _Pragma("unroll")                                                             \
        for (int t = 0; t < 9; t++) {                                                 \
            float f = (t & 1) ? f2[t >> 1].y : f2[t >> 1].x;                          \
            f = fmaxf(f, 0.f);                                                        \
            float sv = f * e[t] * inv;                                                \
            hb[t] = bfbits(sv);                                                       \
            lb[t] = bfbits(sv - bf2f(hb[t]));                                         \
        }                                                                             \
        unsigned u0 = pack2(hb[0], hb[1]), u1 = pack2(hb[2], hb[3]);                  \
        unsigned u2 = pack2(hb[4], hb[5]), u3 = pack2(hb[6], hb[7]);                  \
        unsigned u4 = pack2(hb[8], lb[0]), u5 = pack2(lb[1], lb[2]);                  \
        unsigned u6 = pack2(lb[3], lb[4]), u7 = pack2(lb[5], lb[6]);                  \
        unsigned u8 = pack2(lb[7], lb[8]);                                            \
        uint4* ap = (uint4*)(smA + (cb) * (128 * A_STRIDE) + tid * A_STRIDE);         \
        ap[0] = make_uint4(u0, u1, u2, u3);                                           \
        ap[1] = make_uint4(u4, u5, u6, u7);                                           \
        ap[2] = make_uint4(u8, u0, u1, u2);                                           \
        ap[3] = make_uint4(u3, (unsigned)hb[8], 0u, 0u);                              \
    } while (0)

    #pragma unroll
    for (int j = 0; j < 4; j++) {
        int i = tid + j * 128;
        if (i < 390) {
            int r = i / 130, col = i - r * 130;
            smRows[r * 132 + col] = rowval(upb, 0, gy - 1 + r, col - 1);
        }
    }
    if (tid < SMALLC) smSmall[tid] = g_small[tid];
    if (tid < 64) smBias[tid] = bconv[tid];
    __syncthreads();

    int boff = (lane * 16 + ng * 8) >> 2;
    const uint4* wbp = (const uint4*)g_wbf;
    uint4 b00 = wbp[boff], b01 = wbp[boff + 1], b10 = wbp[boff + 128], b11 = wbp[boff + 129];

    PHASE_A(0);
    #pragma unroll
    for (int j = 0; j < 4; j++) {
        int i = tid + j * 128;
        if (i < 390) {
            int r = i / 130, col = i - r * 130;
            smRows[396 + r * 132 + col] = rowval(upb, 1, gy - 1 + r, col - 1);
        }
    }
    if (tid < SMALLC) smSmall[SMALLC + tid] = g_small[SMALLC + tid];
    __syncthreads();

    for (int c = 1; c < CINC; c++) {
        int pb = (c - 1) & 1, cb = c & 1;

        float rt[4] = {0.f, 0.f, 0.f, 0.f};
        float rs = 0.f;
        if (c + 1 < CINC) {
            #pragma unroll
            for (int j = 0; j < 4; j++) {
                int i = tid + j * 128;
                if (i < 390) {
                    int r = i / 130, col = i - r * 130;
                    rt[j] = rowval(upb, c + 1, gy - 1 + r, col - 1);
                }
            }
            if (tid < SMALLC) rs = g_small[(c + 1) * SMALLC + tid];
        }

        {
            unsigned abase = abase0 + pb * (128 * A_STRIDE * 4);
            unsigned bh0[8] = {b00.x, b00.y, b00.z, b00.w, b01.x, b01.y, b01.z, b01.w};
            unsigned bh1[8] = {b10.x, b10.y, b10.z, b10.w, b11.x, b11.y, b11.z, b11.w};
            #pragma unroll
            for (int mt = 0; mt < 4; mt++) {
                unsigned a0, a1, a2, a3;
                ldsm4(a0, a1, a2, a3, abase + mt * (16 * 80));
                #pragma unroll
                for (int nt = 0; nt < 4; nt++)
                    mma_bf16(acc[mt][nt], a0, a1, a2, a3, bh0[nt * 2], bh0[nt * 2 + 1]);
                unsigned c0, c1r, c2, c3;
                ldsm4(c0, c1r, c2, c3, abase + mt * (16 * 80) + 32);
                #pragma unroll
                for (int nt = 0; nt < 4; nt++)
                    mma_bf16(acc[mt][nt], c0, c1r, c2, c3, bh1[nt * 2], bh1[nt * 2 + 1]);
            }
        }

        wbp = (const uint4*)(g_wbf + c * 1024);
        b00 = wbp[boff]; b01 = wbp[boff + 1]; b10 = wbp[boff + 128]; b11 = wbp[boff + 129];

        PHASE_A(cb);

        if (c + 1 < CINC) {
            #pragma unroll
            for (int j = 0; j < 4; j++) {
                int i = tid + j * 128;
                if (i < 390) {
                    int r = i / 130, col = i - r * 130;
                    smRows[pb * 396 + r * 132 + col] = rt[j];
                }
            }
            if (tid < SMALLC) smSmall[pb * SMALLC + tid] = rs;
        }
        __syncthreads();
    }

    {
        unsigned abase = abase0 + ((CINC - 1) & 1) * (128 * A_STRIDE * 4);
        unsigned bh0[8] = {b00.x, b00.y, b00.z, b00.w, b01.x, b01.y, b01.z, b01.w};
        unsigned bh1[8] = {b10.x, b10.y, b10.z, b10.w, b11.x, b11.y, b11.z, b11.w};
        #pragma unroll
        for (int mt = 0; mt < 4; mt++) {
            unsigned a0, a1, a2, a3;
            ldsm4(a0, a1, a2, a3, abase + mt * (16 * 80));
            #pragma unroll
            for (int nt = 0; nt < 4; nt++)
                mma_bf16(acc[mt][nt], a0, a1, a2, a3, bh0[nt * 2], bh0[nt * 2 + 1]);
            unsigned c0, c1r, c2, c3;
            ldsm4(c0, c1r, c2, c3, abase + mt * (16 * 80) + 32);
            #pragma unroll
            for (int nt = 0; nt < 4; nt++)
                mma_bf16(acc[mt][nt], c0, c1r, c2, c3, bh1[nt * 2], bh1[nt * 2 + 1]);
        }
    }
    __syncthreads();

    float* trans = (float*)smc;
    #pragma unroll
    for (int mt = 0; mt < 4; mt++) {
        int px = mg * 64 + mt * 16 + gid;
        #pragma unroll
        for (int nt = 0; nt < 4; nt++) {
            int n = ng * 32 + nt * 8 + tig * 2;
            trans[n * 132 + px]           = acc[mt][nt][0];
            trans[(n + 1) * 132 + px]     = acc[mt][nt][1];
            trans[n * 132 + px + 8]       = acc[mt][nt][2];
            trans[(n + 1) * 132 + px + 8] = acc[mt][nt][3];
        }
    }
    __syncthreads();
    #pragma unroll
    for (int cc = 0; cc < 16; cc++) {
        int col = w * 16 + cc;
        int oc = (col & 1) ? (64 + (col >> 1)) : (col >> 1);
        float bias = smBias[col];
        float4 v = *(const float4*)(trans + col * 132 + lane * 4);
        v.x += bias; v.y += bias; v.z += bias; v.w += bias;
        *(float4*)(out + ((b * 128 + oc) << 14) + gy * 128 + lane * 4) = v;
    }
    #undef PHASE_A
}

extern "C" void kernel_launch(void* const* d_in, const int* in_sizes, int n_in,
                              void* d_out, int out_size) {
    const float* x     = (const float*)d_in[0];
    const float* wsq   = (const float*)d_in[1];
    const float* wgw   = (const float*)d_in[2];
    const float* wgf   = (const float*)d_in[3];
    const float* gamma = (const float*)d_in[4];
    const float* beta  = (const float*)d_in[5];
    const float* mean  = (const float*)d_in[6];
    const float* var   = (const float*)d_in[7];
    const float* wconv = (const float*)d_in[8];
    const float* bconv = (const float*)d_in[9];
    float* out = (float*)d_out;

    int prep_elems = 32768 + CINC * 1024 + CINC * SMALLC;
    prep_kernel<<<(prep_elems + 255) / 256, 256>>>(wsq, wgf, gamma, beta, mean, var, wgw, wconv);
    squeeze_kernel<<<2048, 128>>>(x, out);
    carafe_kernel<<<dim3(128, BATCH), 128>>>(bconv, out);
}